// round 1
// baseline (speedup 1.0000x reference)
#include <cuda_runtime.h>
#include <cuda_bf16.h>
#include <math.h>

#define NN 20000
#define EE 320000
#define BB 64
#define HH 4
#define DD 64
#define HD 256
#define NUM_ACT 100

// ---------------- scratch (device globals; no allocation) ----------------
__device__ __align__(16) float g_xl[NN * HD];
__device__ __align__(16) float g_xr[NN * HD];
__device__ __align__(16) float g_h [NN * HD];
__device__ __align__(16) float g_acc[NN * HD];
__device__ __align__(16) float g_s  [EE * HH];
__device__ float g_smax [NN * HH];
__device__ float g_denom[NN * HH];
__device__ __align__(16) float g_feats[BB * HD];
__device__ float g_cnt[BB];

// ---------------- helpers ----------------
__device__ __forceinline__ void atomicMaxF(float* addr, float v) {
    if (v >= 0.0f) atomicMax((int*)addr, __float_as_int(v));
    else           atomicMin((unsigned int*)addr, __float_as_uint(v));
}

__device__ __forceinline__ void red_add_v4(float* p, float a, float b, float c, float d) {
    asm volatile("red.global.add.v4.f32 [%0], {%1,%2,%3,%4};"
                 :: "l"(p), "f"(a), "f"(b), "f"(c), "f"(d) : "memory");
}

// ---------------- layer-1 transform: x[N,4] -> xl,xr [N,256] ----------------
__global__ __launch_bounds__(256) void k_gemm1(const float* __restrict__ x,
                                               const float* __restrict__ Wl, const float* __restrict__ bl,
                                               const float* __restrict__ Wr, const float* __restrict__ br) {
    int n = blockIdx.x;
    int j = threadIdx.x;
    __shared__ float xs[4];
    if (j < 4) xs[j] = x[n * 4 + j];
    __syncthreads();
    float al = bl[j], ar = br[j];
#pragma unroll
    for (int k = 0; k < 4; k++) {
        float a = xs[k];
        al += a * Wl[k * HD + j];
        ar += a * Wr[k * HD + j];
    }
    g_xl[n * HD + j] = al;
    g_xr[n * HD + j] = ar;
}

// ---------------- layer-2 dual GEMM: g_h[N,256] @ W[256,256] (x2) ----------------
__global__ __launch_bounds__(256) void k_gemm2(const float* __restrict__ Wl, const float* __restrict__ bl,
                                               const float* __restrict__ Wr, const float* __restrict__ br) {
    __shared__ __align__(16) float Ash[32 * 256];   // [r][k]
    int row0 = blockIdx.x * 32;
    int tid = threadIdx.x;
#pragma unroll
    for (int i = 0; i < 32; i++)
        Ash[i * 256 + tid] = g_h[(row0 + i) * HD + tid];   // coalesced, conflict-free
    __syncthreads();

    float accL[32], accR[32];
#pragma unroll
    for (int r = 0; r < 32; r++) { accL[r] = 0.f; accR[r] = 0.f; }
    const int j = tid;

    for (int k0 = 0; k0 < 256; k0 += 4) {
        float wl0 = Wl[(k0 + 0) * HD + j], wl1 = Wl[(k0 + 1) * HD + j];
        float wl2 = Wl[(k0 + 2) * HD + j], wl3 = Wl[(k0 + 3) * HD + j];
        float wr0 = Wr[(k0 + 0) * HD + j], wr1 = Wr[(k0 + 1) * HD + j];
        float wr2 = Wr[(k0 + 2) * HD + j], wr3 = Wr[(k0 + 3) * HD + j];
#pragma unroll
        for (int r = 0; r < 32; r++) {
            float4 a = *(const float4*)&Ash[r * 256 + k0];   // broadcast LDS.128
            accL[r] += a.x * wl0 + a.y * wl1 + a.z * wl2 + a.w * wl3;
            accR[r] += a.x * wr0 + a.y * wr1 + a.z * wr2 + a.w * wr3;
        }
    }
    float blj = bl[j], brj = br[j];
#pragma unroll
    for (int r = 0; r < 32; r++) {
        g_xl[(row0 + r) * HD + j] = accL[r] + blj;
        g_xr[(row0 + r) * HD + j] = accR[r] + brj;
    }
}

// ---------------- init smax to -inf ----------------
__global__ void k_init_smax(void) {
    int i = blockIdx.x * blockDim.x + threadIdx.x;
    if (i < NN * HH) g_smax[i] = -INFINITY;
}

// ---------------- edge scores + segment max (warp per edge) ----------------
__global__ __launch_bounds__(256) void k_edge_score(const int* __restrict__ ei,
                                                    const float* __restrict__ ea,
                                                    const float* __restrict__ We,
                                                    const float* __restrict__ att) {
    int w = (blockIdx.x * blockDim.x + threadIdx.x) >> 5;
    int lane = threadIdx.x & 31;
    if (w >= EE) return;
    int src = ei[w];
    int dst = ei[EE + w];
    float eav = __ldg(&ea[w]);
    const float* xlp = g_xl + (size_t)src * HD;
    const float* xrp = g_xr + (size_t)dst * HD;
#pragma unroll
    for (int h = 0; h < HH; h++) {
        int i0 = h * 64 + lane;
        float m0 = xlp[i0]      + xrp[i0]      + eav * __ldg(&We[i0]);
        float m1 = xlp[i0 + 32] + xrp[i0 + 32] + eav * __ldg(&We[i0 + 32]);
        m0 = m0 > 0.f ? m0 : 0.2f * m0;
        m1 = m1 > 0.f ? m1 : 0.2f * m1;
        float v = m0 * __ldg(&att[i0]) + m1 * __ldg(&att[i0 + 32]);
#pragma unroll
        for (int o = 16; o; o >>= 1) v += __shfl_down_sync(0xffffffffu, v, o);
        if (lane == 0) {
            g_s[w * HH + h] = v;
            atomicMaxF(&g_smax[dst * HH + h], v);
        }
    }
}

// ---------------- exp(s - smax[dst]) and denom (thread per edge*head) ----------------
__global__ void k_edge_norm(const int* __restrict__ ei) {
    int t = blockIdx.x * blockDim.x + threadIdx.x;
    if (t >= EE * HH) return;
    int e = t >> 2, h = t & 3;
    int dst = ei[EE + e];
    float a = expf(g_s[t] - g_smax[dst * HH + h]);
    g_s[t] = a;
    atomicAdd(&g_denom[dst * HH + h], a);
}

// ---------------- aggregate alpha * xl[src] into g_acc (warp per edge) ----------------
__global__ __launch_bounds__(256) void k_edge_aggr(const int* __restrict__ ei) {
    int w = (blockIdx.x * blockDim.x + threadIdx.x) >> 5;
    int lane = threadIdx.x & 31;
    if (w >= EE) return;
    int src = ei[w];
    int dst = ei[EE + w];
    int h = lane >> 3;                            // lane*8 / 64
    float alpha = g_s[w * HH + h] / (g_denom[dst * HH + h] + 1e-16f);
    const float4* xl4 = (const float4*)(g_xl + (size_t)src * HD) + lane * 2;
    float4 a = xl4[0];
    float4 b = xl4[1];
    float* op = g_acc + (size_t)dst * HD + lane * 8;
    red_add_v4(op,     alpha * a.x, alpha * a.y, alpha * a.z, alpha * a.w);
    red_add_v4(op + 4, alpha * b.x, alpha * b.y, alpha * b.z, alpha * b.w);
}

// ---------------- bias + relu: g_h = relu(g_acc + bias) ----------------
__global__ void k_bias_relu(const float* __restrict__ bias) {
    int idx = blockIdx.x * blockDim.x + threadIdx.x;
    if (idx >= NN * HD) return;
    g_h[idx] = fmaxf(g_acc[idx] + bias[idx & (HD - 1)], 0.0f);
}

// ---------------- pooling: sums + counts per graph ----------------
__global__ void k_pool(const int* __restrict__ batch) {
    int idx = blockIdx.x * blockDim.x + threadIdx.x;   // (n, q) q in [0,64)
    if (idx >= NN * 64) return;
    int n = idx >> 6, q = idx & 63;
    int b = batch[n];
    float4 v = ((const float4*)g_h)[idx];
    red_add_v4(g_feats + b * HD + q * 4, v.x, v.y, v.z, v.w);
    if (q == 0) atomicAdd(&g_cnt[b], 1.0f);
}

// ---------------- heads: actor/critic MLPs + log_softmax (block per graph) ----------------
__global__ __launch_bounds__(128) void k_head(
    const float* __restrict__ Wc1, const float* __restrict__ bc1,
    const float* __restrict__ Wc2, const float* __restrict__ bc2,
    const float* __restrict__ Wc3, const float* __restrict__ bc3,
    const float* __restrict__ Wa1, const float* __restrict__ ba1,
    const float* __restrict__ Wa2, const float* __restrict__ ba2,
    const float* __restrict__ Wa3, const float* __restrict__ ba3,
    const int* __restrict__ action, float* __restrict__ out) {
    int b = blockIdx.x;
    int t = threadIdx.x;
    __shared__ float f[256], h1[128], h2[64], lg[NUM_ACT];

    float cnt = fmaxf(g_cnt[b], 1.0f);
    for (int j = t; j < 256; j += 128) f[j] = g_feats[b * HD + j] / cnt;
    __syncthreads();

    // actor
    {
        float acc = ba1[t];
        for (int k = 0; k < 256; k++) acc += f[k] * Wa1[k * 128 + t];
        h1[t] = fmaxf(acc, 0.f);
    }
    __syncthreads();
    if (t < 64) {
        float acc = ba2[t];
        for (int k = 0; k < 128; k++) acc += h1[k] * Wa2[k * 64 + t];
        h2[t] = fmaxf(acc, 0.f);
    }
    __syncthreads();
    if (t < NUM_ACT) {
        float acc = ba3[t];
        for (int k = 0; k < 64; k++) acc += h2[k] * Wa3[k * NUM_ACT + t];
        lg[t] = acc;
        out[b * NUM_ACT + t] = acc;
    }
    __syncthreads();
    // critic (reuse h1/h2)
    {
        float acc = bc1[t];
        for (int k = 0; k < 256; k++) acc += f[k] * Wc1[k * 128 + t];
        h1[t] = fmaxf(acc, 0.f);
    }
    __syncthreads();
    if (t < 64) {
        float acc = bc2[t];
        for (int k = 0; k < 128; k++) acc += h1[k] * Wc2[k * 64 + t];
        h2[t] = fmaxf(acc, 0.f);
    }
    __syncthreads();
    if (t == 0) {
        float v = bc3[0];
        for (int k = 0; k < 64; k++) v += h2[k] * Wc3[k];
        float mx = -INFINITY;
        for (int i = 0; i < NUM_ACT; i++) mx = fmaxf(mx, lg[i]);
        float se = 0.f;
        for (int i = 0; i < NUM_ACT; i++) se += expf(lg[i] - mx);
        float lse = logf(se) + mx;
        float ent = 0.f;
        for (int i = 0; i < NUM_ACT; i++) {
            float lp = lg[i] - lse;
            ent -= expf(lp) * lp;
        }
        out[BB * NUM_ACT + b]           = lg[action[b]] - lse;   // log_prob
        out[BB * NUM_ACT + BB + b]      = ent;                   // entropy
        out[BB * NUM_ACT + 2 * BB + b]  = v;                     // value
    }
}

// ---------------- launch ----------------
extern "C" void kernel_launch(void* const* d_in, const int* in_sizes, int n_in,
                              void* d_out, int out_size) {
    const float* x      = (const float*)d_in[0];
    const int*   ei     = (const int*)  d_in[1];
    const float* ea     = (const float*)d_in[2];
    const int*   batch  = (const int*)  d_in[3];
    const int*   action = (const int*)  d_in[4];
    const float *Wl1 = (const float*)d_in[5],  *bl1 = (const float*)d_in[6];
    const float *Wr1 = (const float*)d_in[7],  *br1 = (const float*)d_in[8];
    const float *We1 = (const float*)d_in[9],  *att1 = (const float*)d_in[10], *b1 = (const float*)d_in[11];
    const float *Wl2 = (const float*)d_in[12], *bl2 = (const float*)d_in[13];
    const float *Wr2 = (const float*)d_in[14], *br2 = (const float*)d_in[15];
    const float *We2 = (const float*)d_in[16], *att2 = (const float*)d_in[17], *b2 = (const float*)d_in[18];
    const float *Wc1 = (const float*)d_in[19], *bc1 = (const float*)d_in[20];
    const float *Wc2 = (const float*)d_in[21], *bc2 = (const float*)d_in[22];
    const float *Wc3 = (const float*)d_in[23], *bc3 = (const float*)d_in[24];
    const float *Wa1 = (const float*)d_in[25], *ba1 = (const float*)d_in[26];
    const float *Wa2 = (const float*)d_in[27], *ba2 = (const float*)d_in[28];
    const float *Wa3 = (const float*)d_in[29], *ba3 = (const float*)d_in[30];
    float* out = (float*)d_out;

    void *p_acc, *p_denom, *p_feats, *p_cnt;
    cudaGetSymbolAddress(&p_acc,   g_acc);
    cudaGetSymbolAddress(&p_denom, g_denom);
    cudaGetSymbolAddress(&p_feats, g_feats);
    cudaGetSymbolAddress(&p_cnt,   g_cnt);

    // ---- layer 1 ----
    k_gemm1<<<NN, 256>>>(x, Wl1, bl1, Wr1, br1);
    k_init_smax<<<(NN * HH + 255) / 256, 256>>>();
    cudaMemsetAsync(p_denom, 0, (size_t)NN * HH * sizeof(float));
    k_edge_score<<<EE / 8, 256>>>(ei, ea, We1, att1);
    k_edge_norm<<<(EE * HH + 255) / 256, 256>>>(ei);
    cudaMemsetAsync(p_acc, 0, (size_t)NN * HD * sizeof(float));
    k_edge_aggr<<<EE / 8, 256>>>(ei);
    k_bias_relu<<<(NN * HD + 255) / 256, 256>>>(b1);

    // ---- layer 2 ----
    k_gemm2<<<NN / 32, 256>>>(Wl2, bl2, Wr2, br2);
    k_init_smax<<<(NN * HH + 255) / 256, 256>>>();
    cudaMemsetAsync(p_denom, 0, (size_t)NN * HH * sizeof(float));
    k_edge_score<<<EE / 8, 256>>>(ei, ea, We2, att2);
    k_edge_norm<<<(EE * HH + 255) / 256, 256>>>(ei);
    cudaMemsetAsync(p_acc, 0, (size_t)NN * HD * sizeof(float));
    k_edge_aggr<<<EE / 8, 256>>>(ei);
    k_bias_relu<<<(NN * HD + 255) / 256, 256>>>(b2);

    // ---- pooling + heads ----
    cudaMemsetAsync(p_feats, 0, (size_t)BB * HD * sizeof(float));
    cudaMemsetAsync(p_cnt,   0, (size_t)BB * sizeof(float));
    k_pool<<<(NN * 64 + 255) / 256, 256>>>(batch);
    k_head<<<BB, 128>>>(Wc1, bc1, Wc2, bc2, Wc3, bc3,
                        Wa1, ba1, Wa2, ba2, Wa3, ba3, action, out);
}

// round 2
// speedup vs baseline: 2.4385x; 2.4385x over previous
#include <cuda_runtime.h>
#include <cuda_bf16.h>
#include <math.h>

#define NN 20000
#define EE 320000
#define BB 64
#define HD 256
#define NUM_ACT 100

// ---------------- scratch (device globals; no allocation) ----------------
__device__ int   g_deg[NN];
__device__ int   g_rowptr[NN + 1];
__device__ int   g_cursor[NN];
__device__ int   g_csr_src[EE];
__device__ float g_csr_ea[EE];
__device__ __align__(16) float g_h [NN * HD];
__device__ __align__(16) float g_xl[NN * HD];
__device__ __align__(16) float g_xr[NN * HD];
__device__ __align__(16) float g_feats[BB * HD];
__device__ float g_cnt[BB];

// ---------------- helpers ----------------
__device__ __forceinline__ void red_add_v4(float* p, float a, float b, float c, float d) {
    asm volatile("red.global.add.v4.f32 [%0], {%1,%2,%3,%4};"
                 :: "l"(p), "f"(a), "f"(b), "f"(c), "f"(d) : "memory");
}
__device__ __forceinline__ unsigned long long pk2(float x, float y) {
    unsigned long long r;
    asm("mov.b64 %0, {%1,%2};" : "=l"(r) : "f"(x), "f"(y));
    return r;
}
__device__ __forceinline__ void fma2(unsigned long long& d, unsigned long long a, unsigned long long b) {
    asm("fma.rn.f32x2 %0, %1, %2, %0;" : "+l"(d) : "l"(a), "l"(b));
}
__device__ __forceinline__ float2 up2(unsigned long long v) {
    float2 r;
    asm("mov.b64 {%0,%1}, %2;" : "=f"(r.x), "=f"(r.y) : "l"(v));
    return r;
}

// ================= CSR build =================
__global__ void k_deg(const int* __restrict__ ei) {
    int e = blockIdx.x * blockDim.x + threadIdx.x;
    if (e < EE) atomicAdd(&g_deg[ei[EE + e]], 1);
}

__global__ __launch_bounds__(1024) void k_scan(void) {
    __shared__ int s[1024];
    const int C = 20;                       // 1024*20 >= 20000
    int t = threadIdx.x;
    int base = t * C;
    int local[C];
    int sum = 0;
#pragma unroll
    for (int i = 0; i < C; i++) {
        int idx = base + i;
        int d = (idx < NN) ? g_deg[idx] : 0;
        local[i] = d;
        sum += d;
    }
    s[t] = sum;
    __syncthreads();
    for (int off = 1; off < 1024; off <<= 1) {
        int v = (t >= off) ? s[t - off] : 0;
        __syncthreads();
        s[t] += v;
        __syncthreads();
    }
    int run = (t == 0) ? 0 : s[t - 1];
#pragma unroll
    for (int i = 0; i < C; i++) {
        int idx = base + i;
        if (idx < NN) {
            g_rowptr[idx] = run;
            g_cursor[idx] = run;
            run += local[i];
        }
    }
    if (t == 1023) g_rowptr[NN] = EE;
}

__global__ void k_fill(const int* __restrict__ ei, const float* __restrict__ ea) {
    int e = blockIdx.x * blockDim.x + threadIdx.x;
    if (e >= EE) return;
    int dst = ei[EE + e];
    int pos = atomicAdd(&g_cursor[dst], 1);
    g_csr_src[pos] = ei[e];
    g_csr_ea[pos]  = ea[e];
}

// ================= layer-1 fused attention (low-rank; x is [N,4]) =================
// warp per dst node; lane owns dims [lane*8, lane*8+8) (head = lane>>3).
__global__ __launch_bounds__(256) void k_attn1(
    const float* __restrict__ x,
    const float* __restrict__ Wl, const float* __restrict__ bl,
    const float* __restrict__ Wr, const float* __restrict__ br,
    const float* __restrict__ We, const float* __restrict__ att,
    const float* __restrict__ bias) {
    int warp = (blockIdx.x * blockDim.x + threadIdx.x) >> 5;
    int lane = threadIdx.x & 31;
    if (warp >= NN) return;
    int n = warp;
    int d0 = lane * 8;

    // per-lane weight slices in registers
    float wl_[32];
#pragma unroll
    for (int k = 0; k < 4; k++) {
        float4 a = *(const float4*)&Wl[k * HD + d0];
        float4 b = *(const float4*)&Wl[k * HD + d0 + 4];
        wl_[k * 8 + 0] = a.x; wl_[k * 8 + 1] = a.y; wl_[k * 8 + 2] = a.z; wl_[k * 8 + 3] = a.w;
        wl_[k * 8 + 4] = b.x; wl_[k * 8 + 5] = b.y; wl_[k * 8 + 6] = b.z; wl_[k * 8 + 7] = b.w;
    }
    float bl_[8], We_[8], att_[8];
    {
        float4 a = *(const float4*)&bl[d0],  b = *(const float4*)&bl[d0 + 4];
        bl_[0]=a.x; bl_[1]=a.y; bl_[2]=a.z; bl_[3]=a.w; bl_[4]=b.x; bl_[5]=b.y; bl_[6]=b.z; bl_[7]=b.w;
        float4 c = *(const float4*)&We[d0],  d = *(const float4*)&We[d0 + 4];
        We_[0]=c.x; We_[1]=c.y; We_[2]=c.z; We_[3]=c.w; We_[4]=d.x; We_[5]=d.y; We_[6]=d.z; We_[7]=d.w;
        float4 e = *(const float4*)&att[d0], f = *(const float4*)&att[d0 + 4];
        att_[0]=e.x; att_[1]=e.y; att_[2]=e.z; att_[3]=e.w; att_[4]=f.x; att_[5]=f.y; att_[6]=f.z; att_[7]=f.w;
    }

    // xr for this dst (computed once)
    float4 xd = *(const float4*)&x[n * 4];
    float xr_[8];
#pragma unroll
    for (int j = 0; j < 8; j++) {
        int d = d0 + j;
        xr_[j] = br[d] + xd.x * Wr[0 * HD + d] + xd.y * Wr[1 * HD + d]
                       + xd.z * Wr[2 * HD + d] + xd.w * Wr[3 * HD + d];
    }

    int beg = g_rowptr[n], end = g_rowptr[n + 1];
    float m_run = -INFINITY, l = 0.0f;
    float acc[8];
#pragma unroll
    for (int j = 0; j < 8; j++) acc[j] = 0.0f;

    for (int i = beg; i < end; i++) {
        int src = g_csr_src[i];
        float eav = g_csr_ea[i];
        float4 xs = *(const float4*)&x[src * 4];
        float xl[8];
        float p = 0.0f;
#pragma unroll
        for (int j = 0; j < 8; j++) {
            float v = bl_[j] + xs.x * wl_[j] + xs.y * wl_[8 + j]
                             + xs.z * wl_[16 + j] + xs.w * wl_[24 + j];
            xl[j] = v;
            float mm = v + xr_[j] + eav * We_[j];
            mm = mm > 0.0f ? mm : 0.2f * mm;
            p += mm * att_[j];
        }
        // reduce over the 8-lane head group
        p += __shfl_xor_sync(0xffffffffu, p, 1);
        p += __shfl_xor_sync(0xffffffffu, p, 2);
        p += __shfl_xor_sync(0xffffffffu, p, 4);
        // online softmax update
        float newm = fmaxf(m_run, p);
        float c = __expf(m_run - newm);
        float w = __expf(p - newm);
        l = l * c + w;
#pragma unroll
        for (int j = 0; j < 8; j++) acc[j] = acc[j] * c + w * xl[j];
        m_run = newm;
    }
    float inv = 1.0f / (l + 1e-16f);
    float4 oa, ob;
    float4 ba = *(const float4*)&bias[d0], bb = *(const float4*)&bias[d0 + 4];
    oa.x = fmaxf(acc[0] * inv + ba.x, 0.f); oa.y = fmaxf(acc[1] * inv + ba.y, 0.f);
    oa.z = fmaxf(acc[2] * inv + ba.z, 0.f); oa.w = fmaxf(acc[3] * inv + ba.w, 0.f);
    ob.x = fmaxf(acc[4] * inv + bb.x, 0.f); ob.y = fmaxf(acc[5] * inv + bb.y, 0.f);
    ob.z = fmaxf(acc[6] * inv + bb.z, 0.f); ob.w = fmaxf(acc[7] * inv + bb.w, 0.f);
    *(float4*)&g_h[(size_t)n * HD + d0]     = oa;
    *(float4*)&g_h[(size_t)n * HD + d0 + 4] = ob;
}

// ================= layer-2 dual GEMM, packed f32x2 (FFMA2) =================
__global__ __launch_bounds__(256) void k_gemm2(const float* __restrict__ Wl, const float* __restrict__ bl,
                                               const float* __restrict__ Wr, const float* __restrict__ br) {
    __shared__ __align__(16) float2 Ash[16 * 256];   // [row-pair][k]
    int row0 = blockIdx.x * 32;
    int tid = threadIdx.x;
#pragma unroll
    for (int rp = 0; rp < 16; rp++)
        Ash[rp * 256 + tid] = make_float2(g_h[(size_t)(row0 + 2 * rp) * HD + tid],
                                          g_h[(size_t)(row0 + 2 * rp + 1) * HD + tid]);
    __syncthreads();

    unsigned long long accL[16], accR[16];
#pragma unroll
    for (int rp = 0; rp < 16; rp++) { accL[rp] = 0ull; accR[rp] = 0ull; }
    const int j = tid;

    for (int k0 = 0; k0 < 256; k0 += 2) {
        float wl0 = Wl[k0 * HD + j], wl1 = Wl[(k0 + 1) * HD + j];
        float wr0 = Wr[k0 * HD + j], wr1 = Wr[(k0 + 1) * HD + j];
        unsigned long long wl0p = pk2(wl0, wl0), wl1p = pk2(wl1, wl1);
        unsigned long long wr0p = pk2(wr0, wr0), wr1p = pk2(wr1, wr1);
#pragma unroll
        for (int rp = 0; rp < 16; rp++) {
            ulonglong2 a = *(const ulonglong2*)&Ash[rp * 256 + k0];  // 2 rows x 2 k's
            fma2(accL[rp], a.x, wl0p);
            fma2(accL[rp], a.y, wl1p);
            fma2(accR[rp], a.x, wr0p);
            fma2(accR[rp], a.y, wr1p);
        }
    }
    float blj = bl[j], brj = br[j];
#pragma unroll
    for (int rp = 0; rp < 16; rp++) {
        float2 L = up2(accL[rp]);
        float2 R = up2(accR[rp]);
        g_xl[(size_t)(row0 + 2 * rp) * HD + j]     = L.x + blj;
        g_xl[(size_t)(row0 + 2 * rp + 1) * HD + j] = L.y + blj;
        g_xr[(size_t)(row0 + 2 * rp) * HD + j]     = R.x + brj;
        g_xr[(size_t)(row0 + 2 * rp + 1) * HD + j] = R.y + brj;
    }
}

// ================= layer-2 fused attention + pooling =================
__global__ __launch_bounds__(256) void k_attn2(
    const float* __restrict__ We, const float* __restrict__ att,
    const float* __restrict__ bias, const int* __restrict__ batch) {
    int warp = (blockIdx.x * blockDim.x + threadIdx.x) >> 5;
    int lane = threadIdx.x & 31;
    if (warp >= NN) return;
    int n = warp;
    int d0 = lane * 8;

    float We_[8], att_[8], xr_[8];
    {
        float4 c = *(const float4*)&We[d0],  d = *(const float4*)&We[d0 + 4];
        We_[0]=c.x; We_[1]=c.y; We_[2]=c.z; We_[3]=c.w; We_[4]=d.x; We_[5]=d.y; We_[6]=d.z; We_[7]=d.w;
        float4 e = *(const float4*)&att[d0], f = *(const float4*)&att[d0 + 4];
        att_[0]=e.x; att_[1]=e.y; att_[2]=e.z; att_[3]=e.w; att_[4]=f.x; att_[5]=f.y; att_[6]=f.z; att_[7]=f.w;
        float4 a = *(const float4*)&g_xr[(size_t)n * HD + d0];
        float4 b = *(const float4*)&g_xr[(size_t)n * HD + d0 + 4];
        xr_[0]=a.x; xr_[1]=a.y; xr_[2]=a.z; xr_[3]=a.w; xr_[4]=b.x; xr_[5]=b.y; xr_[6]=b.z; xr_[7]=b.w;
    }

    int beg = g_rowptr[n], end = g_rowptr[n + 1];
    float m_run = -INFINITY, l = 0.0f;
    float acc[8];
#pragma unroll
    for (int j = 0; j < 8; j++) acc[j] = 0.0f;

    for (int i = beg; i < end; i++) {
        int src = g_csr_src[i];
        float eav = g_csr_ea[i];
        const float* xp = &g_xl[(size_t)src * HD + d0];
        float4 a = *(const float4*)xp;
        float4 b = *(const float4*)(xp + 4);
        float xl[8] = {a.x, a.y, a.z, a.w, b.x, b.y, b.z, b.w};
        float p = 0.0f;
#pragma unroll
        for (int j = 0; j < 8; j++) {
            float mm = xl[j] + xr_[j] + eav * We_[j];
            mm = mm > 0.0f ? mm : 0.2f * mm;
            p += mm * att_[j];
        }
        p += __shfl_xor_sync(0xffffffffu, p, 1);
        p += __shfl_xor_sync(0xffffffffu, p, 2);
        p += __shfl_xor_sync(0xffffffffu, p, 4);
        float newm = fmaxf(m_run, p);
        float c = __expf(m_run - newm);
        float w = __expf(p - newm);
        l = l * c + w;
#pragma unroll
        for (int j = 0; j < 8; j++) acc[j] = acc[j] * c + w * xl[j];
        m_run = newm;
    }
    float inv = 1.0f / (l + 1e-16f);
    float4 ba = *(const float4*)&bias[d0], bb = *(const float4*)&bias[d0 + 4];
    float v0 = fmaxf(acc[0] * inv + ba.x, 0.f), v1 = fmaxf(acc[1] * inv + ba.y, 0.f);
    float v2 = fmaxf(acc[2] * inv + ba.z, 0.f), v3 = fmaxf(acc[3] * inv + ba.w, 0.f);
    float v4 = fmaxf(acc[4] * inv + bb.x, 0.f), v5 = fmaxf(acc[5] * inv + bb.y, 0.f);
    float v6 = fmaxf(acc[6] * inv + bb.z, 0.f), v7 = fmaxf(acc[7] * inv + bb.w, 0.f);
    int b = batch[n];
    red_add_v4(&g_feats[b * HD + d0],     v0, v1, v2, v3);
    red_add_v4(&g_feats[b * HD + d0 + 4], v4, v5, v6, v7);
    if (lane == 0) atomicAdd(&g_cnt[b], 1.0f);
}

// ================= heads: actor/critic MLPs + log_softmax =================
__global__ __launch_bounds__(128) void k_head(
    const float* __restrict__ Wc1, const float* __restrict__ bc1,
    const float* __restrict__ Wc2, const float* __restrict__ bc2,
    const float* __restrict__ Wc3, const float* __restrict__ bc3,
    const float* __restrict__ Wa1, const float* __restrict__ ba1,
    const float* __restrict__ Wa2, const float* __restrict__ ba2,
    const float* __restrict__ Wa3, const float* __restrict__ ba3,
    const int* __restrict__ action, float* __restrict__ out) {
    int b = blockIdx.x;
    int t = threadIdx.x;
    __shared__ float f[256], h1[128], h2[64], lg[NUM_ACT];

    float cnt = fmaxf(g_cnt[b], 1.0f);
    for (int j = t; j < 256; j += 128) f[j] = g_feats[b * HD + j] / cnt;
    __syncthreads();

    {   // actor
        float acc = ba1[t];
        for (int k = 0; k < 256; k++) acc += f[k] * Wa1[k * 128 + t];
        h1[t] = fmaxf(acc, 0.f);
    }
    __syncthreads();
    if (t < 64) {
        float acc = ba2[t];
        for (int k = 0; k < 128; k++) acc += h1[k] * Wa2[k * 64 + t];
        h2[t] = fmaxf(acc, 0.f);
    }
    __syncthreads();
    if (t < NUM_ACT) {
        float acc = ba3[t];
        for (int k = 0; k < 64; k++) acc += h2[k] * Wa3[k * NUM_ACT + t];
        lg[t] = acc;
        out[b * NUM_ACT + t] = acc;
    }
    __syncthreads();
    {   // critic (reuse h1/h2)
        float acc = bc1[t];
        for (int k = 0; k < 256; k++) acc += f[k] * Wc1[k * 128 + t];
        h1[t] = fmaxf(acc, 0.f);
    }
    __syncthreads();
    if (t < 64) {
        float acc = bc2[t];
        for (int k = 0; k < 128; k++) acc += h1[k] * Wc2[k * 64 + t];
        h2[t] = fmaxf(acc, 0.f);
    }
    __syncthreads();
    if (t == 0) {
        float v = bc3[0];
        for (int k = 0; k < 64; k++) v += h2[k] * Wc3[k];
        float mx = -INFINITY;
        for (int i = 0; i < NUM_ACT; i++) mx = fmaxf(mx, lg[i]);
        float se = 0.f;
        for (int i = 0; i < NUM_ACT; i++) se += expf(lg[i] - mx);
        float lse = logf(se) + mx;
        float ent = 0.f;
        for (int i = 0; i < NUM_ACT; i++) {
            float lp = lg[i] - lse;
            ent -= expf(lp) * lp;
        }
        out[BB * NUM_ACT + b]          = lg[action[b]] - lse;   // log_prob
        out[BB * NUM_ACT + BB + b]     = ent;                   // entropy
        out[BB * NUM_ACT + 2 * BB + b] = v;                     // value
    }
}

// ---------------- launch ----------------
extern "C" void kernel_launch(void* const* d_in, const int* in_sizes, int n_in,
                              void* d_out, int out_size) {
    const float* x      = (const float*)d_in[0];
    const int*   ei     = (const int*)  d_in[1];
    const float* ea     = (const float*)d_in[2];
    const int*   batch  = (const int*)  d_in[3];
    const int*   action = (const int*)  d_in[4];
    const float *Wl1 = (const float*)d_in[5],  *bl1 = (const float*)d_in[6];
    const float *Wr1 = (const float*)d_in[7],  *br1 = (const float*)d_in[8];
    const float *We1 = (const float*)d_in[9],  *att1 = (const float*)d_in[10], *b1 = (const float*)d_in[11];
    const float *Wl2 = (const float*)d_in[12], *bl2 = (const float*)d_in[13];
    const float *Wr2 = (const float*)d_in[14], *br2 = (const float*)d_in[15];
    const float *We2 = (const float*)d_in[16], *att2 = (const float*)d_in[17], *b2 = (const float*)d_in[18];
    const float *Wc1 = (const float*)d_in[19], *bc1 = (const float*)d_in[20];
    const float *Wc2 = (const float*)d_in[21], *bc2 = (const float*)d_in[22];
    const float *Wc3 = (const float*)d_in[23], *bc3 = (const float*)d_in[24];
    const float *Wa1 = (const float*)d_in[25], *ba1 = (const float*)d_in[26];
    const float *Wa2 = (const float*)d_in[27], *ba2 = (const float*)d_in[28];
    const float *Wa3 = (const float*)d_in[29], *ba3 = (const float*)d_in[30];
    float* out = (float*)d_out;

    void *p_deg, *p_feats, *p_cnt;
    cudaGetSymbolAddress(&p_deg,   g_deg);
    cudaGetSymbolAddress(&p_feats, g_feats);
    cudaGetSymbolAddress(&p_cnt,   g_cnt);

    // CSR build
    cudaMemsetAsync(p_deg, 0, NN * sizeof(int));
    k_deg<<<(EE + 255) / 256, 256>>>(ei);
    k_scan<<<1, 1024>>>();
    k_fill<<<(EE + 255) / 256, 256>>>(ei, ea);

    // layer 1 (fused low-rank attention)
    k_attn1<<<NN / 8, 256>>>(x, Wl1, bl1, Wr1, br1, We1, att1, b1);

    // layer 2 transform + fused attention + pooling
    k_gemm2<<<NN / 32, 256>>>(Wl2, bl2, Wr2, br2);
    cudaMemsetAsync(p_feats, 0, (size_t)BB * HD * sizeof(float));
    cudaMemsetAsync(p_cnt,   0, (size_t)BB * sizeof(float));
    k_attn2<<<NN / 8, 256>>>(We2, att2, b2, batch);

    // heads
    k_head<<<BB, 128>>>(Wc1, bc1, Wc2, bc2, Wc3, bc3,
                        Wa1, ba1, Wa2, ba2, Wa3, ba3, action, out);
}

// round 3
// speedup vs baseline: 2.6353x; 1.0807x over previous
#include <cuda_runtime.h>
#include <cuda_bf16.h>
#include <math.h>

#define NN 20000
#define EE 320000
#define BB 64
#define HD 256
#define NUM_ACT 100

// ---------------- scratch (device globals; no allocation) ----------------
__device__ int   g_deg[NN];
__device__ int   g_rowptr[NN + 1];
__device__ int   g_cursor[NN];
__device__ __align__(16) int2 g_csr[EE];          // (src, ea bits)
__device__ __align__(16) float g_h [NN * HD];
__device__ __align__(16) float g_xl[NN * HD];
__device__ __align__(16) float g_xr[NN * HD];
__device__ __align__(16) float g_feats[BB * HD];
__device__ float g_cnt[BB];

// ---------------- helpers ----------------
__device__ __forceinline__ void red_add_v4(float* p, float a, float b, float c, float d) {
    asm volatile("red.global.add.v4.f32 [%0], {%1,%2,%3,%4};"
                 :: "l"(p), "f"(a), "f"(b), "f"(c), "f"(d) : "memory");
}
__device__ __forceinline__ unsigned long long pk2(float x, float y) {
    unsigned long long r;
    asm("mov.b64 %0, {%1,%2};" : "=l"(r) : "f"(x), "f"(y));
    return r;
}
__device__ __forceinline__ void fma2(unsigned long long& d, unsigned long long a, unsigned long long b) {
    asm("fma.rn.f32x2 %0, %1, %2, %0;" : "+l"(d) : "l"(a), "l"(b));
}
__device__ __forceinline__ float2 up2(unsigned long long v) {
    float2 r;
    asm("mov.b64 {%0,%1}, %2;" : "=f"(r.x), "=f"(r.y) : "l"(v));
    return r;
}
__device__ __forceinline__ float wred8(float v) {
    v += __shfl_xor_sync(0xffffffffu, v, 1);
    v += __shfl_xor_sync(0xffffffffu, v, 2);
    v += __shfl_xor_sync(0xffffffffu, v, 4);
    return v;
}

// ================= CSR build =================
__global__ void k_deg(const int* __restrict__ ei) {
    int e = blockIdx.x * blockDim.x + threadIdx.x;
    if (e < EE) atomicAdd(&g_deg[ei[EE + e]], 1);
}

__global__ __launch_bounds__(1024) void k_scan(void) {
    __shared__ int s[1024];
    const int C = 20;
    int t = threadIdx.x;
    int base = t * C;
    int local[C];
    int sum = 0;
#pragma unroll
    for (int i = 0; i < C; i++) {
        int idx = base + i;
        int d = (idx < NN) ? g_deg[idx] : 0;
        local[i] = d;
        sum += d;
    }
    s[t] = sum;
    __syncthreads();
    for (int off = 1; off < 1024; off <<= 1) {
        int v = (t >= off) ? s[t - off] : 0;
        __syncthreads();
        s[t] += v;
        __syncthreads();
    }
    int run = (t == 0) ? 0 : s[t - 1];
#pragma unroll
    for (int i = 0; i < C; i++) {
        int idx = base + i;
        if (idx < NN) {
            g_rowptr[idx] = run;
            g_cursor[idx] = run;
            run += local[i];
        }
    }
    if (t == 1023) g_rowptr[NN] = EE;
}

__global__ void k_fill(const int* __restrict__ ei, const float* __restrict__ ea) {
    int e = blockIdx.x * blockDim.x + threadIdx.x;
    if (e >= EE) return;
    int dst = ei[EE + e];
    int pos = atomicAdd(&g_cursor[dst], 1);
    g_csr[pos] = make_int2(ei[e], __float_as_int(ea[e]));
}

// ================= layer-1 fused attention (rank-4 collapse) =================
// warp per dst node; lane owns dims [lane*8, lane*8+8) (head = lane>>3).
__global__ __launch_bounds__(256) void k_attn1(
    const float* __restrict__ x,
    const float* __restrict__ Wl, const float* __restrict__ bl,
    const float* __restrict__ Wr, const float* __restrict__ br,
    const float* __restrict__ We, const float* __restrict__ att,
    const float* __restrict__ bias) {
    int warp = (blockIdx.x * blockDim.x + threadIdx.x) >> 5;
    int lane = threadIdx.x & 31;
    if (warp >= NN) return;
    int n = warp;
    int d0 = lane * 8;

    // per-lane weight slices
    float wl_[32];
#pragma unroll
    for (int k = 0; k < 4; k++) {
        float4 a = *(const float4*)&Wl[k * HD + d0];
        float4 b = *(const float4*)&Wl[k * HD + d0 + 4];
        wl_[k*8+0]=a.x; wl_[k*8+1]=a.y; wl_[k*8+2]=a.z; wl_[k*8+3]=a.w;
        wl_[k*8+4]=b.x; wl_[k*8+5]=b.y; wl_[k*8+6]=b.z; wl_[k*8+7]=b.w;
    }
    float We_[8], att_[8], xrb_[8];
    {
        float4 c = *(const float4*)&We[d0],  d = *(const float4*)&We[d0 + 4];
        We_[0]=c.x; We_[1]=c.y; We_[2]=c.z; We_[3]=c.w; We_[4]=d.x; We_[5]=d.y; We_[6]=d.z; We_[7]=d.w;
        float4 e = *(const float4*)&att[d0], f = *(const float4*)&att[d0 + 4];
        att_[0]=e.x; att_[1]=e.y; att_[2]=e.z; att_[3]=e.w; att_[4]=f.x; att_[5]=f.y; att_[6]=f.z; att_[7]=f.w;
    }
    // xrb = xr(dst) + bl   (bl folded into the score constant)
    float4 xd = *(const float4*)&x[n * 4];
#pragma unroll
    for (int j = 0; j < 8; j++) {
        int d = d0 + j;
        xrb_[j] = br[d] + bl[d]
                + xd.x * Wr[0 * HD + d] + xd.y * Wr[1 * HD + d]
                + xd.z * Wr[2 * HD + d] + xd.w * Wr[3 * HD + d];
    }

    int beg = g_rowptr[n], end = g_rowptr[n + 1];
    float m_run = -INFINITY, l = 0.0f;
    float ax = 0.f, ay = 0.f, az = 0.f, aw = 0.f;   // softmax-weighted x (4-dim, warp-uniform)

    for (int i = beg; i < end; i += 4) {
        int i1 = (i + 1 < end) ? i + 1 : i;
        int i2 = (i + 2 < end) ? i + 2 : i;
        int i3 = (i + 3 < end) ? i + 3 : i;
        int2 e0 = g_csr[i], e1 = g_csr[i1], e2 = g_csr[i2], e3 = g_csr[i3];
        float4 xs0 = *(const float4*)&x[e0.x * 4];
        float4 xs1 = *(const float4*)&x[e1.x * 4];
        float4 xs2 = *(const float4*)&x[e2.x * 4];
        float4 xs3 = *(const float4*)&x[e3.x * 4];
        float ea0 = __int_as_float(e0.y), ea1 = __int_as_float(e1.y);
        float ea2 = __int_as_float(e2.y), ea3 = __int_as_float(e3.y);

        float p0 = 0.f, p1 = 0.f, p2 = 0.f, p3 = 0.f;
#pragma unroll
        for (int j = 0; j < 8; j++) {
            float base = xrb_[j];
            float w0j = wl_[j], w1j = wl_[8+j], w2j = wl_[16+j], w3j = wl_[24+j];
            float wej = We_[j], atj = att_[j];
            float v0 = base + xs0.x*w0j + xs0.y*w1j + xs0.z*w2j + xs0.w*w3j + ea0*wej;
            float v1 = base + xs1.x*w0j + xs1.y*w1j + xs1.z*w2j + xs1.w*w3j + ea1*wej;
            float v2 = base + xs2.x*w0j + xs2.y*w1j + xs2.z*w2j + xs2.w*w3j + ea2*wej;
            float v3 = base + xs3.x*w0j + xs3.y*w1j + xs3.z*w2j + xs3.w*w3j + ea3*wej;
            v0 = v0 > 0.f ? v0 : 0.2f*v0;
            v1 = v1 > 0.f ? v1 : 0.2f*v1;
            v2 = v2 > 0.f ? v2 : 0.2f*v2;
            v3 = v3 > 0.f ? v3 : 0.2f*v3;
            p0 += v0*atj; p1 += v1*atj; p2 += v2*atj; p3 += v3*atj;
        }
        p0 += __shfl_xor_sync(0xffffffffu, p0, 1);
        p1 += __shfl_xor_sync(0xffffffffu, p1, 1);
        p2 += __shfl_xor_sync(0xffffffffu, p2, 1);
        p3 += __shfl_xor_sync(0xffffffffu, p3, 1);
        p0 += __shfl_xor_sync(0xffffffffu, p0, 2);
        p1 += __shfl_xor_sync(0xffffffffu, p1, 2);
        p2 += __shfl_xor_sync(0xffffffffu, p2, 2);
        p3 += __shfl_xor_sync(0xffffffffu, p3, 2);
        p0 += __shfl_xor_sync(0xffffffffu, p0, 4);
        p1 += __shfl_xor_sync(0xffffffffu, p1, 4);
        p2 += __shfl_xor_sync(0xffffffffu, p2, 4);
        p3 += __shfl_xor_sync(0xffffffffu, p3, 4);
        if (i + 1 >= end) p1 = -INFINITY;
        if (i + 2 >= end) p2 = -INFINITY;
        if (i + 3 >= end) p3 = -INFINITY;

        float mb = fmaxf(fmaxf(p0, p1), fmaxf(p2, p3));
        float newm = fmaxf(m_run, mb);
        float c  = __expf(m_run - newm);
        float w0 = __expf(p0 - newm), w1 = __expf(p1 - newm);
        float w2 = __expf(p2 - newm), w3 = __expf(p3 - newm);
        l  = l * c + (w0 + w1) + (w2 + w3);
        ax = ax * c + w0*xs0.x + w1*xs1.x + w2*xs2.x + w3*xs3.x;
        ay = ay * c + w0*xs0.y + w1*xs1.y + w2*xs2.y + w3*xs3.y;
        az = az * c + w0*xs0.z + w1*xs1.z + w2*xs2.z + w3*xs3.z;
        aw = aw * c + w0*xs0.w + w1*xs1.w + w2*xs2.w + w3*xs3.w;
        m_run = newm;
    }
    float inv = 1.0f / (l + 1e-16f);
    ax *= inv; ay *= inv; az *= inv; aw *= inv;
    float have = (end > beg) ? 1.0f : 0.0f;        // deg==0 -> out = relu(bias)
    float o[8];
#pragma unroll
    for (int j = 0; j < 8; j++) {
        int d = d0 + j;
        float v = bias[d] + have * (bl[d] + ax*wl_[j] + ay*wl_[8+j] + az*wl_[16+j] + aw*wl_[24+j]);
        o[j] = fmaxf(v, 0.0f);
    }
    *(float4*)&g_h[(size_t)n * HD + d0]     = make_float4(o[0], o[1], o[2], o[3]);
    *(float4*)&g_h[(size_t)n * HD + d0 + 4] = make_float4(o[4], o[5], o[6], o[7]);
}

// ================= layer-2 dual GEMM, packed f32x2 (FFMA2) =================
__global__ __launch_bounds__(256) void k_gemm2(const float* __restrict__ Wl, const float* __restrict__ bl,
                                               const float* __restrict__ Wr, const float* __restrict__ br) {
    __shared__ __align__(16) float2 Ash[16 * 256];   // [row-pair][k]
    int row0 = blockIdx.x * 32;
    int tid = threadIdx.x;
#pragma unroll
    for (int rp = 0; rp < 16; rp++)
        Ash[rp * 256 + tid] = make_float2(g_h[(size_t)(row0 + 2 * rp) * HD + tid],
                                          g_h[(size_t)(row0 + 2 * rp + 1) * HD + tid]);
    __syncthreads();

    unsigned long long accL[16], accR[16];
#pragma unroll
    for (int rp = 0; rp < 16; rp++) { accL[rp] = 0ull; accR[rp] = 0ull; }
    const int j = tid;

    for (int k0 = 0; k0 < 256; k0 += 2) {
        float wl0 = Wl[k0 * HD + j], wl1 = Wl[(k0 + 1) * HD + j];
        float wr0 = Wr[k0 * HD + j], wr1 = Wr[(k0 + 1) * HD + j];
        unsigned long long wl0p = pk2(wl0, wl0), wl1p = pk2(wl1, wl1);
        unsigned long long wr0p = pk2(wr0, wr0), wr1p = pk2(wr1, wr1);
#pragma unroll
        for (int rp = 0; rp < 16; rp++) {
            ulonglong2 a = *(const ulonglong2*)&Ash[rp * 256 + k0];
            fma2(accL[rp], a.x, wl0p);
            fma2(accL[rp], a.y, wl1p);
            fma2(accR[rp], a.x, wr0p);
            fma2(accR[rp], a.y, wr1p);
        }
    }
    float blj = bl[j], brj = br[j];
#pragma unroll
    for (int rp = 0; rp < 16; rp++) {
        float2 L = up2(accL[rp]);
        float2 R = up2(accR[rp]);
        g_xl[(size_t)(row0 + 2 * rp) * HD + j]     = L.x + blj;
        g_xl[(size_t)(row0 + 2 * rp + 1) * HD + j] = L.y + blj;
        g_xr[(size_t)(row0 + 2 * rp) * HD + j]     = R.x + brj;
        g_xr[(size_t)(row0 + 2 * rp + 1) * HD + j] = R.y + brj;
    }
}

// ================= layer-2 fused attention + pooling (batch-4) =================
__global__ __launch_bounds__(256) void k_attn2(
    const float* __restrict__ We, const float* __restrict__ att,
    const float* __restrict__ bias, const int* __restrict__ batch) {
    int warp = (blockIdx.x * blockDim.x + threadIdx.x) >> 5;
    int lane = threadIdx.x & 31;
    if (warp >= NN) return;
    int n = warp;
    int d0 = lane * 8;

    float We_[8], att_[8], xr_[8];
    {
        float4 c = *(const float4*)&We[d0],  d = *(const float4*)&We[d0 + 4];
        We_[0]=c.x; We_[1]=c.y; We_[2]=c.z; We_[3]=c.w; We_[4]=d.x; We_[5]=d.y; We_[6]=d.z; We_[7]=d.w;
        float4 e = *(const float4*)&att[d0], f = *(const float4*)&att[d0 + 4];
        att_[0]=e.x; att_[1]=e.y; att_[2]=e.z; att_[3]=e.w; att_[4]=f.x; att_[5]=f.y; att_[6]=f.z; att_[7]=f.w;
        float4 a = *(const float4*)&g_xr[(size_t)n * HD + d0];
        float4 b = *(const float4*)&g_xr[(size_t)n * HD + d0 + 4];
        xr_[0]=a.x; xr_[1]=a.y; xr_[2]=a.z; xr_[3]=a.w; xr_[4]=b.x; xr_[5]=b.y; xr_[6]=b.z; xr_[7]=b.w;
    }

    int beg = g_rowptr[n], end = g_rowptr[n + 1];
    float m_run = -INFINITY, l = 0.0f;
    float acc[8];
#pragma unroll
    for (int j = 0; j < 8; j++) acc[j] = 0.0f;

    for (int i = beg; i < end; i += 4) {
        int i1 = (i + 1 < end) ? i + 1 : i;
        int i2 = (i + 2 < end) ? i + 2 : i;
        int i3 = (i + 3 < end) ? i + 3 : i;
        int2 e0 = g_csr[i], e1 = g_csr[i1], e2 = g_csr[i2], e3 = g_csr[i3];
        const float4* q0 = (const float4*)&g_xl[(size_t)e0.x * HD + d0];
        const float4* q1 = (const float4*)&g_xl[(size_t)e1.x * HD + d0];
        const float4* q2 = (const float4*)&g_xl[(size_t)e2.x * HD + d0];
        const float4* q3 = (const float4*)&g_xl[(size_t)e3.x * HD + d0];
        float4 a0 = q0[0], b0 = q0[1];
        float4 a1 = q1[0], b1 = q1[1];
        float4 a2 = q2[0], b2 = q2[1];
        float4 a3 = q3[0], b3 = q3[1];
        float xl0[8] = {a0.x,a0.y,a0.z,a0.w,b0.x,b0.y,b0.z,b0.w};
        float xl1[8] = {a1.x,a1.y,a1.z,a1.w,b1.x,b1.y,b1.z,b1.w};
        float xl2[8] = {a2.x,a2.y,a2.z,a2.w,b2.x,b2.y,b2.z,b2.w};
        float xl3[8] = {a3.x,a3.y,a3.z,a3.w,b3.x,b3.y,b3.z,b3.w};
        float ea0 = __int_as_float(e0.y), ea1 = __int_as_float(e1.y);
        float ea2 = __int_as_float(e2.y), ea3 = __int_as_float(e3.y);

        float p0 = 0.f, p1 = 0.f, p2 = 0.f, p3 = 0.f;
#pragma unroll
        for (int j = 0; j < 8; j++) {
            float base = xr_[j], wej = We_[j], atj = att_[j];
            float v0 = xl0[j] + base + ea0*wej;
            float v1 = xl1[j] + base + ea1*wej;
            float v2 = xl2[j] + base + ea2*wej;
            float v3 = xl3[j] + base + ea3*wej;
            v0 = v0 > 0.f ? v0 : 0.2f*v0;
            v1 = v1 > 0.f ? v1 : 0.2f*v1;
            v2 = v2 > 0.f ? v2 : 0.2f*v2;
            v3 = v3 > 0.f ? v3 : 0.2f*v3;
            p0 += v0*atj; p1 += v1*atj; p2 += v2*atj; p3 += v3*atj;
        }
        p0 += __shfl_xor_sync(0xffffffffu, p0, 1);
        p1 += __shfl_xor_sync(0xffffffffu, p1, 1);
        p2 += __shfl_xor_sync(0xffffffffu, p2, 1);
        p3 += __shfl_xor_sync(0xffffffffu, p3, 1);
        p0 += __shfl_xor_sync(0xffffffffu, p0, 2);
        p1 += __shfl_xor_sync(0xffffffffu, p1, 2);
        p2 += __shfl_xor_sync(0xffffffffu, p2, 2);
        p3 += __shfl_xor_sync(0xffffffffu, p3, 2);
        p0 += __shfl_xor_sync(0xffffffffu, p0, 4);
        p1 += __shfl_xor_sync(0xffffffffu, p1, 4);
        p2 += __shfl_xor_sync(0xffffffffu, p2, 4);
        p3 += __shfl_xor_sync(0xffffffffu, p3, 4);
        if (i + 1 >= end) p1 = -INFINITY;
        if (i + 2 >= end) p2 = -INFINITY;
        if (i + 3 >= end) p3 = -INFINITY;

        float mb = fmaxf(fmaxf(p0, p1), fmaxf(p2, p3));
        float newm = fmaxf(m_run, mb);
        float c  = __expf(m_run - newm);
        float w0 = __expf(p0 - newm), w1 = __expf(p1 - newm);
        float w2 = __expf(p2 - newm), w3 = __expf(p3 - newm);
        l = l * c + (w0 + w1) + (w2 + w3);
#pragma unroll
        for (int j = 0; j < 8; j++)
            acc[j] = acc[j] * c + w0*xl0[j] + w1*xl1[j] + w2*xl2[j] + w3*xl3[j];
        m_run = newm;
    }
    float inv = 1.0f / (l + 1e-16f);
    float4 ba = *(const float4*)&bias[d0], bb = *(const float4*)&bias[d0 + 4];
    float v0 = fmaxf(acc[0]*inv + ba.x, 0.f), v1 = fmaxf(acc[1]*inv + ba.y, 0.f);
    float v2 = fmaxf(acc[2]*inv + ba.z, 0.f), v3 = fmaxf(acc[3]*inv + ba.w, 0.f);
    float v4 = fmaxf(acc[4]*inv + bb.x, 0.f), v5 = fmaxf(acc[5]*inv + bb.y, 0.f);
    float v6 = fmaxf(acc[6]*inv + bb.z, 0.f), v7 = fmaxf(acc[7]*inv + bb.w, 0.f);
    int b = batch[n];
    red_add_v4(&g_feats[b * HD + d0],     v0, v1, v2, v3);
    red_add_v4(&g_feats[b * HD + d0 + 4], v4, v5, v6, v7);
    if (lane == 0) atomicAdd(&g_cnt[b], 1.0f);
}

// ================= heads =================
__global__ __launch_bounds__(128) void k_head(
    const float* __restrict__ Wc1, const float* __restrict__ bc1,
    const float* __restrict__ Wc2, const float* __restrict__ bc2,
    const float* __restrict__ Wc3, const float* __restrict__ bc3,
    const float* __restrict__ Wa1, const float* __restrict__ ba1,
    const float* __restrict__ Wa2, const float* __restrict__ ba2,
    const float* __restrict__ Wa3, const float* __restrict__ ba3,
    const int* __restrict__ action, float* __restrict__ out) {
    int b = blockIdx.x;
    int t = threadIdx.x;
    __shared__ float f[256], h1[128], h2[64], lg[NUM_ACT];

    float cnt = fmaxf(g_cnt[b], 1.0f);
    for (int j = t; j < 256; j += 128) f[j] = g_feats[b * HD + j] / cnt;
    __syncthreads();

    {   // actor
        float acc = ba1[t];
        for (int k = 0; k < 256; k++) acc += f[k] * Wa1[k * 128 + t];
        h1[t] = fmaxf(acc, 0.f);
    }
    __syncthreads();
    if (t < 64) {
        float acc = ba2[t];
        for (int k = 0; k < 128; k++) acc += h1[k] * Wa2[k * 64 + t];
        h2[t] = fmaxf(acc, 0.f);
    }
    __syncthreads();
    if (t < NUM_ACT) {
        float acc = ba3[t];
        for (int k = 0; k < 64; k++) acc += h2[k] * Wa3[k * NUM_ACT + t];
        lg[t] = acc;
        out[b * NUM_ACT + t] = acc;
    }
    __syncthreads();
    {   // critic
        float acc = bc1[t];
        for (int k = 0; k < 256; k++) acc += f[k] * Wc1[k * 128 + t];
        h1[t] = fmaxf(acc, 0.f);
    }
    __syncthreads();
    if (t < 64) {
        float acc = bc2[t];
        for (int k = 0; k < 128; k++) acc += h1[k] * Wc2[k * 64 + t];
        h2[t] = fmaxf(acc, 0.f);
    }
    __syncthreads();
    if (t == 0) {
        float v = bc3[0];
        for (int k = 0; k < 64; k++) v += h2[k] * Wc3[k];
        float mx = -INFINITY;
        for (int i = 0; i < NUM_ACT; i++) mx = fmaxf(mx, lg[i]);
        float se = 0.f;
        for (int i = 0; i < NUM_ACT; i++) se += expf(lg[i] - mx);
        float lse = logf(se) + mx;
        float ent = 0.f;
        for (int i = 0; i < NUM_ACT; i++) {
            float lp = lg[i] - lse;
            ent -= expf(lp) * lp;
        }
        out[BB * NUM_ACT + b]          = lg[action[b]] - lse;
        out[BB * NUM_ACT + BB + b]     = ent;
        out[BB * NUM_ACT + 2 * BB + b] = v;
    }
}

// ---------------- launch ----------------
extern "C" void kernel_launch(void* const* d_in, const int* in_sizes, int n_in,
                              void* d_out, int out_size) {
    const float* x      = (const float*)d_in[0];
    const int*   ei     = (const int*)  d_in[1];
    const float* ea     = (const float*)d_in[2];
    const int*   batch  = (const int*)  d_in[3];
    const int*   action = (const int*)  d_in[4];
    const float *Wl1 = (const float*)d_in[5],  *bl1 = (const float*)d_in[6];
    const float *Wr1 = (const float*)d_in[7],  *br1 = (const float*)d_in[8];
    const float *We1 = (const float*)d_in[9],  *att1 = (const float*)d_in[10], *b1 = (const float*)d_in[11];
    const float *Wl2 = (const float*)d_in[12], *bl2 = (const float*)d_in[13];
    const float *Wr2 = (const float*)d_in[14], *br2 = (const float*)d_in[15];
    const float *We2 = (const float*)d_in[16], *att2 = (const float*)d_in[17], *b2 = (const float*)d_in[18];
    const float *Wc1 = (const float*)d_in[19], *bc1 = (const float*)d_in[20];
    const float *Wc2 = (const float*)d_in[21], *bc2 = (const float*)d_in[22];
    const float *Wc3 = (const float*)d_in[23], *bc3 = (const float*)d_in[24];
    const float *Wa1 = (const float*)d_in[25], *ba1 = (const float*)d_in[26];
    const float *Wa2 = (const float*)d_in[27], *ba2 = (const float*)d_in[28];
    const float *Wa3 = (const float*)d_in[29], *ba3 = (const float*)d_in[30];
    float* out = (float*)d_out;

    void *p_deg, *p_feats, *p_cnt;
    cudaGetSymbolAddress(&p_deg,   g_deg);
    cudaGetSymbolAddress(&p_feats, g_feats);
    cudaGetSymbolAddress(&p_cnt,   g_cnt);

    // CSR build
    cudaMemsetAsync(p_deg, 0, NN * sizeof(int));
    k_deg<<<(EE + 255) / 256, 256>>>(ei);
    k_scan<<<1, 1024>>>();
    k_fill<<<(EE + 255) / 256, 256>>>(ei, ea);

    // layer 1 (fused low-rank attention)
    k_attn1<<<NN / 8, 256>>>(x, Wl1, bl1, Wr1, br1, We1, att1, b1);

    // layer 2 transform + fused attention + pooling
    k_gemm2<<<NN / 32, 256>>>(Wl2, bl2, Wr2, br2);
    cudaMemsetAsync(p_feats, 0, (size_t)BB * HD * sizeof(float));
    cudaMemsetAsync(p_cnt,   0, (size_t)BB * sizeof(float));
    k_attn2<<<NN / 8, 256>>>(We2, att2, b2, batch);

    // heads
    k_head<<<BB, 128>>>(Wc1, bc1, Wc2, bc2, Wc3, bc3,
                        Wa1, ba1, Wa2, ba2, Wa3, ba3, action, out);
}

// round 4
// speedup vs baseline: 2.8498x; 1.0814x over previous
#include <cuda_runtime.h>
#include <cuda_bf16.h>
#include <math.h>

#define NN 20000
#define EE 320000
#define BB 64
#define HD 256
#define NUM_ACT 100

// ---------------- scratch (device globals; no allocation) ----------------
__device__ int   g_deg[NN];
__device__ int   g_rowptr[NN + 1];
__device__ int   g_cursor[NN];
__device__ __align__(16) int2 g_csr[EE];          // (src, ea bits)
__device__ __align__(16) float g_h [NN * HD];
__device__ __align__(16) float g_xl[NN * HD];
__device__ __align__(16) float g_xr[NN * HD];
__device__ __align__(16) float g_feats[BB * HD];
__device__ float g_cnt[BB];

// ---------------- helpers ----------------
__device__ __forceinline__ void red_add_v4(float* p, float a, float b, float c, float d) {
    asm volatile("red.global.add.v4.f32 [%0], {%1,%2,%3,%4};"
                 :: "l"(p), "f"(a), "f"(b), "f"(c), "f"(d) : "memory");
}
__device__ __forceinline__ unsigned long long pk2(float x, float y) {
    unsigned long long r;
    asm("mov.b64 %0, {%1,%2};" : "=l"(r) : "f"(x), "f"(y));
    return r;
}
__device__ __forceinline__ void fma2(unsigned long long& d, unsigned long long a, unsigned long long b) {
    asm("fma.rn.f32x2 %0, %1, %2, %0;" : "+l"(d) : "l"(a), "l"(b));
}
__device__ __forceinline__ float2 up2(unsigned long long v) {
    float2 r;
    asm("mov.b64 {%0,%1}, %2;" : "=f"(r.x), "=f"(r.y) : "l"(v));
    return r;
}

// ================= CSR build =================
__global__ void k_deg(const int* __restrict__ ei) {
    int e = blockIdx.x * blockDim.x + threadIdx.x;
    if (e < EE) atomicAdd(&g_deg[ei[EE + e]], 1);
}

__global__ __launch_bounds__(1024) void k_scan(void) {
    __shared__ int s[1024];
    const int C = 20;
    int t = threadIdx.x;
    int base = t * C;
    int local[C];
    int sum = 0;
#pragma unroll
    for (int i = 0; i < C; i++) {
        int idx = base + i;
        int d = (idx < NN) ? g_deg[idx] : 0;
        local[i] = d;
        sum += d;
    }
    s[t] = sum;
    __syncthreads();
    for (int off = 1; off < 1024; off <<= 1) {
        int v = (t >= off) ? s[t - off] : 0;
        __syncthreads();
        s[t] += v;
        __syncthreads();
    }
    int run = (t == 0) ? 0 : s[t - 1];
#pragma unroll
    for (int i = 0; i < C; i++) {
        int idx = base + i;
        if (idx < NN) {
            g_rowptr[idx] = run;
            g_cursor[idx] = run;
            run += local[i];
        }
    }
    if (t == 1023) g_rowptr[NN] = EE;
}

__global__ void k_fill(const int* __restrict__ ei, const float* __restrict__ ea) {
    int e = blockIdx.x * blockDim.x + threadIdx.x;
    if (e >= EE) return;
    int dst = ei[EE + e];
    int pos = atomicAdd(&g_cursor[dst], 1);
    g_csr[pos] = make_int2(ei[e], __float_as_int(ea[e]));
}

// ================= layer-1 transforms (rank-4): xl1 = x@Wl+bl, xr1 = x@Wr+br ===========
__global__ __launch_bounds__(256) void k_pre1(const float* __restrict__ x,
                                              const float* __restrict__ Wl, const float* __restrict__ bl,
                                              const float* __restrict__ Wr, const float* __restrict__ br) {
    int idx = blockIdx.x * blockDim.x + threadIdx.x;     // over NN*64 float4 slots
    if (idx >= NN * 64) return;
    int n = idx >> 6;
    int c = (idx & 63) << 2;
    float4 xv = ((const float4*)x)[n];
    float xa[4] = {xv.x, xv.y, xv.z, xv.w};
    float4 l = *(const float4*)&bl[c];
    float4 r = *(const float4*)&br[c];
#pragma unroll
    for (int k = 0; k < 4; k++) {
        float4 wl = *(const float4*)&Wl[k * HD + c];
        float4 wr = *(const float4*)&Wr[k * HD + c];
        l.x += xa[k] * wl.x; l.y += xa[k] * wl.y; l.z += xa[k] * wl.z; l.w += xa[k] * wl.w;
        r.x += xa[k] * wr.x; r.y += xa[k] * wr.y; r.z += xa[k] * wr.z; r.w += xa[k] * wr.w;
    }
    ((float4*)g_xl)[idx] = l;
    ((float4*)g_xr)[idx] = r;
}

// ================= unified fused attention (batch-4 online softmax) =================
// POOL=0: write g_h = relu(out + bias).  POOL=1: relu(out + bias) pooled into g_feats.
// warp per dst node; lane owns dims [lane*8, lane*8+8) (head = lane>>3).
template<int POOL>
__global__ __launch_bounds__(128, 5) void k_attn(
    const float* __restrict__ We, const float* __restrict__ att,
    const float* __restrict__ bias, const int* __restrict__ batch) {
    int warp = (blockIdx.x * blockDim.x + threadIdx.x) >> 5;
    int lane = threadIdx.x & 31;
    if (warp >= NN) return;
    int n = warp;
    int d0 = lane * 8;

    float We_[8], a_[8], b_[8], xr_[8];
    {
        float4 c = *(const float4*)&We[d0],  d = *(const float4*)&We[d0 + 4];
        We_[0]=c.x; We_[1]=c.y; We_[2]=c.z; We_[3]=c.w; We_[4]=d.x; We_[5]=d.y; We_[6]=d.z; We_[7]=d.w;
        float4 e = *(const float4*)&att[d0], f = *(const float4*)&att[d0 + 4];
        float at[8] = {e.x,e.y,e.z,e.w,f.x,f.y,f.z,f.w};
#pragma unroll
        for (int j = 0; j < 8; j++) { a_[j] = 0.6f * at[j]; b_[j] = 0.4f * at[j]; }
        float4 g = *(const float4*)&g_xr[(size_t)n * HD + d0];
        float4 h = *(const float4*)&g_xr[(size_t)n * HD + d0 + 4];
        xr_[0]=g.x; xr_[1]=g.y; xr_[2]=g.z; xr_[3]=g.w; xr_[4]=h.x; xr_[5]=h.y; xr_[6]=h.z; xr_[7]=h.w;
    }

    int beg = g_rowptr[n], end = g_rowptr[n + 1];
    float m_run = -INFINITY, l = 0.0f;
    float acc[8];
#pragma unroll
    for (int j = 0; j < 8; j++) acc[j] = 0.0f;

    for (int i = beg; i < end; i += 4) {
        int i1 = (i + 1 < end) ? i + 1 : i;
        int i2 = (i + 2 < end) ? i + 2 : i;
        int i3 = (i + 3 < end) ? i + 3 : i;
        int2 e0 = g_csr[i], e1 = g_csr[i1], e2 = g_csr[i2], e3 = g_csr[i3];
        const float4* q0 = (const float4*)&g_xl[(size_t)e0.x * HD + d0];
        const float4* q1 = (const float4*)&g_xl[(size_t)e1.x * HD + d0];
        const float4* q2 = (const float4*)&g_xl[(size_t)e2.x * HD + d0];
        const float4* q3 = (const float4*)&g_xl[(size_t)e3.x * HD + d0];
        float4 a0 = q0[0], c0 = q0[1];
        float4 a1 = q1[0], c1 = q1[1];
        float4 a2 = q2[0], c2 = q2[1];
        float4 a3 = q3[0], c3 = q3[1];
        float xl0[8] = {a0.x,a0.y,a0.z,a0.w,c0.x,c0.y,c0.z,c0.w};
        float xl1[8] = {a1.x,a1.y,a1.z,a1.w,c1.x,c1.y,c1.z,c1.w};
        float xl2[8] = {a2.x,a2.y,a2.z,a2.w,c2.x,c2.y,c2.z,c2.w};
        float xl3[8] = {a3.x,a3.y,a3.z,a3.w,c3.x,c3.y,c3.z,c3.w};
        float ea0 = __int_as_float(e0.y), ea1 = __int_as_float(e1.y);
        float ea2 = __int_as_float(e2.y), ea3 = __int_as_float(e3.y);

        float p0 = 0.f, p1 = 0.f, p2 = 0.f, p3 = 0.f;
#pragma unroll
        for (int j = 0; j < 8; j++) {
            float wej = We_[j], xrj = xr_[j], aj = a_[j], bj = b_[j];
            float v0 = fmaf(ea0, wej, xrj) + xl0[j];
            float v1 = fmaf(ea1, wej, xrj) + xl1[j];
            float v2 = fmaf(ea2, wej, xrj) + xl2[j];
            float v3 = fmaf(ea3, wej, xrj) + xl3[j];
            p0 = fmaf(aj, v0, p0); p0 = fmaf(bj, fabsf(v0), p0);
            p1 = fmaf(aj, v1, p1); p1 = fmaf(bj, fabsf(v1), p1);
            p2 = fmaf(aj, v2, p2); p2 = fmaf(bj, fabsf(v2), p2);
            p3 = fmaf(aj, v3, p3); p3 = fmaf(bj, fabsf(v3), p3);
        }
        p0 += __shfl_xor_sync(0xffffffffu, p0, 1);
        p1 += __shfl_xor_sync(0xffffffffu, p1, 1);
        p2 += __shfl_xor_sync(0xffffffffu, p2, 1);
        p3 += __shfl_xor_sync(0xffffffffu, p3, 1);
        p0 += __shfl_xor_sync(0xffffffffu, p0, 2);
        p1 += __shfl_xor_sync(0xffffffffu, p1, 2);
        p2 += __shfl_xor_sync(0xffffffffu, p2, 2);
        p3 += __shfl_xor_sync(0xffffffffu, p3, 2);
        p0 += __shfl_xor_sync(0xffffffffu, p0, 4);
        p1 += __shfl_xor_sync(0xffffffffu, p1, 4);
        p2 += __shfl_xor_sync(0xffffffffu, p2, 4);
        p3 += __shfl_xor_sync(0xffffffffu, p3, 4);
        if (i + 1 >= end) p1 = -INFINITY;
        if (i + 2 >= end) p2 = -INFINITY;
        if (i + 3 >= end) p3 = -INFINITY;

        float mb = fmaxf(fmaxf(p0, p1), fmaxf(p2, p3));
        float newm = fmaxf(m_run, mb);
        float c  = __expf(m_run - newm);
        float w0 = __expf(p0 - newm), w1 = __expf(p1 - newm);
        float w2 = __expf(p2 - newm), w3 = __expf(p3 - newm);
        l = l * c + (w0 + w1) + (w2 + w3);
#pragma unroll
        for (int j = 0; j < 8; j++)
            acc[j] = acc[j] * c + w0*xl0[j] + w1*xl1[j] + w2*xl2[j] + w3*xl3[j];
        m_run = newm;
    }
    float inv = 1.0f / (l + 1e-16f);
    float4 ba = *(const float4*)&bias[d0], bb = *(const float4*)&bias[d0 + 4];
    float v0 = fmaxf(fmaf(acc[0], inv, ba.x), 0.f), v1 = fmaxf(fmaf(acc[1], inv, ba.y), 0.f);
    float v2 = fmaxf(fmaf(acc[2], inv, ba.z), 0.f), v3 = fmaxf(fmaf(acc[3], inv, ba.w), 0.f);
    float v4 = fmaxf(fmaf(acc[4], inv, bb.x), 0.f), v5 = fmaxf(fmaf(acc[5], inv, bb.y), 0.f);
    float v6 = fmaxf(fmaf(acc[6], inv, bb.z), 0.f), v7 = fmaxf(fmaf(acc[7], inv, bb.w), 0.f);
    if (POOL == 0) {
        *(float4*)&g_h[(size_t)n * HD + d0]     = make_float4(v0, v1, v2, v3);
        *(float4*)&g_h[(size_t)n * HD + d0 + 4] = make_float4(v4, v5, v6, v7);
    } else {
        int b = batch[n];
        red_add_v4(&g_feats[b * HD + d0],     v0, v1, v2, v3);
        red_add_v4(&g_feats[b * HD + d0 + 4], v4, v5, v6, v7);
        if (lane == 0) atomicAdd(&g_cnt[b], 1.0f);
    }
}

// ================= layer-2 dual GEMM, packed f32x2 (FFMA2) =================
__global__ __launch_bounds__(256) void k_gemm2(const float* __restrict__ Wl, const float* __restrict__ bl,
                                               const float* __restrict__ Wr, const float* __restrict__ br) {
    __shared__ __align__(16) float2 Ash[16 * 256];   // [row-pair][k]
    int row0 = blockIdx.x * 32;
    int tid = threadIdx.x;
#pragma unroll
    for (int rp = 0; rp < 16; rp++)
        Ash[rp * 256 + tid] = make_float2(g_h[(size_t)(row0 + 2 * rp) * HD + tid],
                                          g_h[(size_t)(row0 + 2 * rp + 1) * HD + tid]);
    __syncthreads();

    unsigned long long accL[16], accR[16];
#pragma unroll
    for (int rp = 0; rp < 16; rp++) { accL[rp] = 0ull; accR[rp] = 0ull; }
    const int j = tid;

    for (int k0 = 0; k0 < 256; k0 += 2) {
        float wl0 = Wl[k0 * HD + j], wl1 = Wl[(k0 + 1) * HD + j];
        float wr0 = Wr[k0 * HD + j], wr1 = Wr[(k0 + 1) * HD + j];
        unsigned long long wl0p = pk2(wl0, wl0), wl1p = pk2(wl1, wl1);
        unsigned long long wr0p = pk2(wr0, wr0), wr1p = pk2(wr1, wr1);
#pragma unroll
        for (int rp = 0; rp < 16; rp++) {
            ulonglong2 a = *(const ulonglong2*)&Ash[rp * 256 + k0];
            fma2(accL[rp], a.x, wl0p);
            fma2(accL[rp], a.y, wl1p);
            fma2(accR[rp], a.x, wr0p);
            fma2(accR[rp], a.y, wr1p);
        }
    }
    float blj = bl[j], brj = br[j];
#pragma unroll
    for (int rp = 0; rp < 16; rp++) {
        float2 L = up2(accL[rp]);
        float2 R = up2(accR[rp]);
        g_xl[(size_t)(row0 + 2 * rp) * HD + j]     = L.x + blj;
        g_xl[(size_t)(row0 + 2 * rp + 1) * HD + j] = L.y + blj;
        g_xr[(size_t)(row0 + 2 * rp) * HD + j]     = R.x + brj;
        g_xr[(size_t)(row0 + 2 * rp + 1) * HD + j] = R.y + brj;
    }
}

// ================= heads =================
__global__ __launch_bounds__(128) void k_head(
    const float* __restrict__ Wc1, const float* __restrict__ bc1,
    const float* __restrict__ Wc2, const float* __restrict__ bc2,
    const float* __restrict__ Wc3, const float* __restrict__ bc3,
    const float* __restrict__ Wa1, const float* __restrict__ ba1,
    const float* __restrict__ Wa2, const float* __restrict__ ba2,
    const float* __restrict__ Wa3, const float* __restrict__ ba3,
    const int* __restrict__ action, float* __restrict__ out) {
    int b = blockIdx.x;
    int t = threadIdx.x;
    __shared__ float f[256], h1[128], h2[64], lg[NUM_ACT];

    float cnt = fmaxf(g_cnt[b], 1.0f);
    for (int j = t; j < 256; j += 128) f[j] = g_feats[b * HD + j] / cnt;
    __syncthreads();

    {   // actor
        float acc = ba1[t];
        for (int k = 0; k < 256; k++) acc += f[k] * Wa1[k * 128 + t];
        h1[t] = fmaxf(acc, 0.f);
    }
    __syncthreads();
    if (t < 64) {
        float acc = ba2[t];
        for (int k = 0; k < 128; k++) acc += h1[k] * Wa2[k * 64 + t];
        h2[t] = fmaxf(acc, 0.f);
    }
    __syncthreads();
    if (t < NUM_ACT) {
        float acc = ba3[t];
        for (int k = 0; k < 64; k++) acc += h2[k] * Wa3[k * NUM_ACT + t];
        lg[t] = acc;
        out[b * NUM_ACT + t] = acc;
    }
    __syncthreads();
    {   // critic
        float acc = bc1[t];
        for (int k = 0; k < 256; k++) acc += f[k] * Wc1[k * 128 + t];
        h1[t] = fmaxf(acc, 0.f);
    }
    __syncthreads();
    if (t < 64) {
        float acc = bc2[t];
        for (int k = 0; k < 128; k++) acc += h1[k] * Wc2[k * 64 + t];
        h2[t] = fmaxf(acc, 0.f);
    }
    __syncthreads();
    if (t == 0) {
        float v = bc3[0];
        for (int k = 0; k < 64; k++) v += h2[k] * Wc3[k];
        float mx = -INFINITY;
        for (int i = 0; i < NUM_ACT; i++) mx = fmaxf(mx, lg[i]);
        float se = 0.f;
        for (int i = 0; i < NUM_ACT; i++) se += expf(lg[i] - mx);
        float lse = logf(se) + mx;
        float ent = 0.f;
        for (int i = 0; i < NUM_ACT; i++) {
            float lp = lg[i] - lse;
            ent -= expf(lp) * lp;
        }
        out[BB * NUM_ACT + b]          = lg[action[b]] - lse;
        out[BB * NUM_ACT + BB + b]     = ent;
        out[BB * NUM_ACT + 2 * BB + b] = v;
    }
}

// ---------------- launch ----------------
extern "C" void kernel_launch(void* const* d_in, const int* in_sizes, int n_in,
                              void* d_out, int out_size) {
    const float* x      = (const float*)d_in[0];
    const int*   ei     = (const int*)  d_in[1];
    const float* ea     = (const float*)d_in[2];
    const int*   batch  = (const int*)  d_in[3];
    const int*   action = (const int*)  d_in[4];
    const float *Wl1 = (const float*)d_in[5],  *bl1 = (const float*)d_in[6];
    const float *Wr1 = (const float*)d_in[7],  *br1 = (const float*)d_in[8];
    const float *We1 = (const float*)d_in[9],  *att1 = (const float*)d_in[10], *b1 = (const float*)d_in[11];
    const float *Wl2 = (const float*)d_in[12], *bl2 = (const float*)d_in[13];
    const float *Wr2 = (const float*)d_in[14], *br2 = (const float*)d_in[15];
    const float *We2 = (const float*)d_in[16], *att2 = (const float*)d_in[17], *b2 = (const float*)d_in[18];
    const float *Wc1 = (const float*)d_in[19], *bc1 = (const float*)d_in[20];
    const float *Wc2 = (const float*)d_in[21], *bc2 = (const float*)d_in[22];
    const float *Wc3 = (const float*)d_in[23], *bc3 = (const float*)d_in[24];
    const float *Wa1 = (const float*)d_in[25], *ba1 = (const float*)d_in[26];
    const float *Wa2 = (const float*)d_in[27], *ba2 = (const float*)d_in[28];
    const float *Wa3 = (const float*)d_in[29], *ba3 = (const float*)d_in[30];
    float* out = (float*)d_out;

    void *p_deg, *p_feats, *p_cnt;
    cudaGetSymbolAddress(&p_deg,   g_deg);
    cudaGetSymbolAddress(&p_feats, g_feats);
    cudaGetSymbolAddress(&p_cnt,   g_cnt);

    // side stream for overlapping layer-1 transform with CSR build
    static cudaStream_t s_side = nullptr;
    static cudaEvent_t ev_fork = nullptr, ev_join = nullptr;
    if (s_side == nullptr) {
        cudaStreamCreateWithFlags(&s_side, cudaStreamNonBlocking);
        cudaEventCreateWithFlags(&ev_fork, cudaEventDisableTiming);
        cudaEventCreateWithFlags(&ev_join, cudaEventDisableTiming);
    }

    // fork: layer-1 transform on side stream
    cudaEventRecord(ev_fork, 0);
    cudaStreamWaitEvent(s_side, ev_fork, 0);
    k_pre1<<<(NN * 64 + 255) / 256, 256, 0, s_side>>>(x, Wl1, bl1, Wr1, br1);
    cudaMemsetAsync(p_feats, 0, (size_t)BB * HD * sizeof(float), s_side);
    cudaMemsetAsync(p_cnt,   0, (size_t)BB * sizeof(float), s_side);
    cudaEventRecord(ev_join, s_side);

    // main: CSR build
    cudaMemsetAsync(p_deg, 0, NN * sizeof(int));
    k_deg<<<(EE + 255) / 256, 256>>>(ei);
    k_scan<<<1, 1024>>>();
    k_fill<<<(EE + 255) / 256, 256>>>(ei, ea);

    // join, then layer-1 fused attention
    cudaStreamWaitEvent(0, ev_join, 0);
    k_attn<0><<<NN / 4, 128>>>(We1, att1, b1, batch);

    // layer 2 transform + fused attention + pooling
    k_gemm2<<<NN / 32, 256>>>(Wl2, bl2, Wr2, br2);
    k_attn<1><<<NN / 4, 128>>>(We2, att2, b2, batch);

    // heads
    k_head<<<BB, 128>>>(Wc1, bc1, Wc2, bc2, Wc3, bc3,
                        Wa1, ba1, Wa2, ba2, Wa3, ba3, action, out);
}

// round 5
// speedup vs baseline: 2.8500x; 1.0001x over previous
#include <cuda_runtime.h>
#include <cuda_bf16.h>
#include <math.h>

#define NN 20000
#define EE 320000
#define BB 64
#define HD 256
#define NUM_ACT 100

typedef unsigned long long u64;

// ---------------- scratch (device globals; no allocation) ----------------
__device__ int   g_deg[NN];
__device__ int   g_rowptr[NN + 1];
__device__ int   g_cursor[NN];
__device__ __align__(16) int2 g_csr[EE];          // (src, ea bits)
__device__ __align__(16) float g_h [NN * HD];
__device__ __align__(16) float g_xl[NN * HD];
__device__ __align__(16) float g_xr[NN * HD];
__device__ __align__(16) float g_feats[BB * HD];
__device__ float g_cnt[BB];

// ---------------- helpers ----------------
__device__ __forceinline__ void red_add_v4(float* p, float a, float b, float c, float d) {
    asm volatile("red.global.add.v4.f32 [%0], {%1,%2,%3,%4};"
                 :: "l"(p), "f"(a), "f"(b), "f"(c), "f"(d) : "memory");
}
__device__ __forceinline__ u64 pk2(float x, float y) {
    u64 r;
    asm("mov.b64 %0, {%1,%2};" : "=l"(r) : "f"(x), "f"(y));
    return r;
}
__device__ __forceinline__ void fma2(u64& d, u64 a, u64 b) {
    asm("fma.rn.f32x2 %0, %1, %2, %0;" : "+l"(d) : "l"(a), "l"(b));
}
__device__ __forceinline__ u64 fma2o(u64 a, u64 b, u64 c) {
    u64 r;
    asm("fma.rn.f32x2 %0, %1, %2, %3;" : "=l"(r) : "l"(a), "l"(b), "l"(c));
    return r;
}
__device__ __forceinline__ u64 add2(u64 a, u64 b) {
    u64 r;
    asm("add.rn.f32x2 %0, %1, %2;" : "=l"(r) : "l"(a), "l"(b));
    return r;
}
__device__ __forceinline__ u64 abs2(u64 v) {
    return v & 0x7FFFFFFF7FFFFFFFull;
}
__device__ __forceinline__ float2 up2(u64 v) {
    float2 r;
    asm("mov.b64 {%0,%1}, %2;" : "=f"(r.x), "=f"(r.y) : "l"(v));
    return r;
}

// ================= CSR build =================
__global__ void k_deg(const int* __restrict__ ei) {
    int e = blockIdx.x * blockDim.x + threadIdx.x;
    if (e < EE) atomicAdd(&g_deg[ei[EE + e]], 1);
}

__global__ __launch_bounds__(1024) void k_scan(void) {
    __shared__ int s[1024];
    const int C = 20;
    int t = threadIdx.x;
    int base = t * C;
    int local[C];
    int sum = 0;
#pragma unroll
    for (int i = 0; i < C; i++) {
        int idx = base + i;
        int d = (idx < NN) ? g_deg[idx] : 0;
        local[i] = d;
        sum += d;
    }
    s[t] = sum;
    __syncthreads();
    for (int off = 1; off < 1024; off <<= 1) {
        int v = (t >= off) ? s[t - off] : 0;
        __syncthreads();
        s[t] += v;
        __syncthreads();
    }
    int run = (t == 0) ? 0 : s[t - 1];
#pragma unroll
    for (int i = 0; i < C; i++) {
        int idx = base + i;
        if (idx < NN) {
            g_rowptr[idx] = run;
            g_cursor[idx] = run;
            run += local[i];
        }
    }
    if (t == 1023) g_rowptr[NN] = EE;
}

__global__ void k_fill(const int* __restrict__ ei, const float* __restrict__ ea) {
    int e = blockIdx.x * blockDim.x + threadIdx.x;
    if (e >= EE) return;
    int dst = ei[EE + e];
    int pos = atomicAdd(&g_cursor[dst], 1);
    g_csr[pos] = make_int2(ei[e], __float_as_int(ea[e]));
}

// ================= layer-1 transforms (rank-4) =================
__global__ __launch_bounds__(256) void k_pre1(const float* __restrict__ x,
                                              const float* __restrict__ Wl, const float* __restrict__ bl,
                                              const float* __restrict__ Wr, const float* __restrict__ br) {
    int idx = blockIdx.x * blockDim.x + threadIdx.x;
    if (idx >= NN * 64) return;
    int n = idx >> 6;
    int c = (idx & 63) << 2;
    float4 xv = ((const float4*)x)[n];
    float xa[4] = {xv.x, xv.y, xv.z, xv.w};
    float4 l = *(const float4*)&bl[c];
    float4 r = *(const float4*)&br[c];
#pragma unroll
    for (int k = 0; k < 4; k++) {
        float4 wl = *(const float4*)&Wl[k * HD + c];
        float4 wr = *(const float4*)&Wr[k * HD + c];
        l.x += xa[k] * wl.x; l.y += xa[k] * wl.y; l.z += xa[k] * wl.z; l.w += xa[k] * wl.w;
        r.x += xa[k] * wr.x; r.y += xa[k] * wr.y; r.z += xa[k] * wr.z; r.w += xa[k] * wr.w;
    }
    ((float4*)g_xl)[idx] = l;
    ((float4*)g_xr)[idx] = r;
}

// ================= unified fused attention (no-max streaming softmax, packed f32x2) =====
// warp per dst node; lane owns dims [lane*8, lane*8+8) as 4 f32x2 pairs (head = lane>>3).
template<int POOL>
__global__ __launch_bounds__(128, 5) void k_attn(
    const float* __restrict__ We, const float* __restrict__ att,
    const float* __restrict__ bias, const int* __restrict__ batch) {
    int warp = (blockIdx.x * blockDim.x + threadIdx.x) >> 5;
    int lane = threadIdx.x & 31;
    if (warp >= NN) return;
    int n = warp;
    int d0 = lane * 8;

    // packed per-lane constants: We pairs, 0.6*att & 0.4*att pairs, xr pairs
    u64 We2[4], a2[4], b2[4], xr2[4];
    {
        const ulonglong2* wp = (const ulonglong2*)&We[d0];
        ulonglong2 w01 = wp[0], w23 = wp[1];
        We2[0] = w01.x; We2[1] = w01.y; We2[2] = w23.x; We2[3] = w23.y;
        float4 e = *(const float4*)&att[d0], f = *(const float4*)&att[d0 + 4];
        a2[0] = pk2(0.6f*e.x, 0.6f*e.y); a2[1] = pk2(0.6f*e.z, 0.6f*e.w);
        a2[2] = pk2(0.6f*f.x, 0.6f*f.y); a2[3] = pk2(0.6f*f.z, 0.6f*f.w);
        b2[0] = pk2(0.4f*e.x, 0.4f*e.y); b2[1] = pk2(0.4f*e.z, 0.4f*e.w);
        b2[2] = pk2(0.4f*f.x, 0.4f*f.y); b2[3] = pk2(0.4f*f.z, 0.4f*f.w);
        const ulonglong2* xp = (const ulonglong2*)&g_xr[(size_t)n * HD + d0];
        ulonglong2 x01 = xp[0], x23 = xp[1];
        xr2[0] = x01.x; xr2[1] = x01.y; xr2[2] = x23.x; xr2[3] = x23.y;
    }

    int beg = g_rowptr[n], end = g_rowptr[n + 1];
    float l = 0.0f;
    u64 acc2[4] = {0ull, 0ull, 0ull, 0ull};

    for (int i = beg; i < end; i += 4) {
        int i1 = (i + 1 < end) ? i + 1 : i;
        int i2 = (i + 2 < end) ? i + 2 : i;
        int i3 = (i + 3 < end) ? i + 3 : i;
        int2 e0 = g_csr[i], e1 = g_csr[i1], e2 = g_csr[i2], e3 = g_csr[i3];
        const ulonglong2* q0 = (const ulonglong2*)&g_xl[(size_t)e0.x * HD + d0];
        const ulonglong2* q1 = (const ulonglong2*)&g_xl[(size_t)e1.x * HD + d0];
        const ulonglong2* q2 = (const ulonglong2*)&g_xl[(size_t)e2.x * HD + d0];
        const ulonglong2* q3 = (const ulonglong2*)&g_xl[(size_t)e3.x * HD + d0];
        ulonglong2 A0 = q0[0], B0 = q0[1];
        ulonglong2 A1 = q1[0], B1 = q1[1];
        ulonglong2 A2 = q2[0], B2 = q2[1];
        ulonglong2 A3 = q3[0], B3 = q3[1];
        u64 xl0[4] = {A0.x, A0.y, B0.x, B0.y};
        u64 xl1[4] = {A1.x, A1.y, B1.x, B1.y};
        u64 xl2[4] = {A2.x, A2.y, B2.x, B2.y};
        u64 xl3[4] = {A3.x, A3.y, B3.x, B3.y};
        float ea0 = __int_as_float(e0.y), ea1 = __int_as_float(e1.y);
        float ea2 = __int_as_float(e2.y), ea3 = __int_as_float(e3.y);
        u64 ep0 = pk2(ea0, ea0), ep1 = pk2(ea1, ea1);
        u64 ep2 = pk2(ea2, ea2), ep3 = pk2(ea3, ea3);

        u64 pp0 = 0ull, pp1 = 0ull, pp2 = 0ull, pp3 = 0ull;
#pragma unroll
        for (int jp = 0; jp < 4; jp++) {
            u64 base = fma2o(ep0, We2[jp], xr2[jp]);   // reuse name per edge
            u64 v0 = add2(base, xl0[jp]);
            u64 v1 = add2(fma2o(ep1, We2[jp], xr2[jp]), xl1[jp]);
            u64 v2 = add2(fma2o(ep2, We2[jp], xr2[jp]), xl2[jp]);
            u64 v3 = add2(fma2o(ep3, We2[jp], xr2[jp]), xl3[jp]);
            fma2(pp0, a2[jp], v0); fma2(pp0, b2[jp], abs2(v0));
            fma2(pp1, a2[jp], v1); fma2(pp1, b2[jp], abs2(v1));
            fma2(pp2, a2[jp], v2); fma2(pp2, b2[jp], abs2(v2));
            fma2(pp3, a2[jp], v3); fma2(pp3, b2[jp], abs2(v3));
        }
        float2 f0 = up2(pp0), f1 = up2(pp1), f2 = up2(pp2), f3 = up2(pp3);
        float p0 = f0.x + f0.y, p1 = f1.x + f1.y, p2 = f2.x + f2.y, p3 = f3.x + f3.y;
        p0 += __shfl_xor_sync(0xffffffffu, p0, 1);
        p1 += __shfl_xor_sync(0xffffffffu, p1, 1);
        p2 += __shfl_xor_sync(0xffffffffu, p2, 1);
        p3 += __shfl_xor_sync(0xffffffffu, p3, 1);
        p0 += __shfl_xor_sync(0xffffffffu, p0, 2);
        p1 += __shfl_xor_sync(0xffffffffu, p1, 2);
        p2 += __shfl_xor_sync(0xffffffffu, p2, 2);
        p3 += __shfl_xor_sync(0xffffffffu, p3, 2);
        p0 += __shfl_xor_sync(0xffffffffu, p0, 4);
        p1 += __shfl_xor_sync(0xffffffffu, p1, 4);
        p2 += __shfl_xor_sync(0xffffffffu, p2, 4);
        p3 += __shfl_xor_sync(0xffffffffu, p3, 4);
        if (i + 1 >= end) p1 = -INFINITY;
        if (i + 2 >= end) p2 = -INFINITY;
        if (i + 3 >= end) p3 = -INFINITY;

        // no-max softmax: scores are bounded (|s| << 80), exp() is safe; ratio unchanged
        float w0 = __expf(p0), w1 = __expf(p1), w2 = __expf(p2), w3 = __expf(p3);
        l += (w0 + w1) + (w2 + w3);
        u64 wp0 = pk2(w0, w0), wp1 = pk2(w1, w1), wp2 = pk2(w2, w2), wp3 = pk2(w3, w3);
#pragma unroll
        for (int jp = 0; jp < 4; jp++) {
            fma2(acc2[jp], wp0, xl0[jp]);
            fma2(acc2[jp], wp1, xl1[jp]);
            fma2(acc2[jp], wp2, xl2[jp]);
            fma2(acc2[jp], wp3, xl3[jp]);
        }
    }
    float inv = 1.0f / (l + 1e-16f);
    float2 c0 = up2(acc2[0]), c1 = up2(acc2[1]), c2 = up2(acc2[2]), c3 = up2(acc2[3]);
    float4 ba = *(const float4*)&bias[d0], bb = *(const float4*)&bias[d0 + 4];
    float v0 = fmaxf(fmaf(c0.x, inv, ba.x), 0.f), v1 = fmaxf(fmaf(c0.y, inv, ba.y), 0.f);
    float v2 = fmaxf(fmaf(c1.x, inv, ba.z), 0.f), v3 = fmaxf(fmaf(c1.y, inv, ba.w), 0.f);
    float v4 = fmaxf(fmaf(c2.x, inv, bb.x), 0.f), v5 = fmaxf(fmaf(c2.y, inv, bb.y), 0.f);
    float v6 = fmaxf(fmaf(c3.x, inv, bb.z), 0.f), v7 = fmaxf(fmaf(c3.y, inv, bb.w), 0.f);
    if (POOL == 0) {
        *(float4*)&g_h[(size_t)n * HD + d0]     = make_float4(v0, v1, v2, v3);
        *(float4*)&g_h[(size_t)n * HD + d0 + 4] = make_float4(v4, v5, v6, v7);
    } else {
        int b = batch[n];
        red_add_v4(&g_feats[b * HD + d0],     v0, v1, v2, v3);
        red_add_v4(&g_feats[b * HD + d0 + 4], v4, v5, v6, v7);
        if (lane == 0) atomicAdd(&g_cnt[b], 1.0f);
    }
}

// ================= layer-2 dual GEMM, packed f32x2 (FFMA2) =================
__global__ __launch_bounds__(256) void k_gemm2(const float* __restrict__ Wl, const float* __restrict__ bl,
                                               const float* __restrict__ Wr, const float* __restrict__ br) {
    __shared__ __align__(16) float2 Ash[16 * 256];   // [row-pair][k]
    int row0 = blockIdx.x * 32;
    int tid = threadIdx.x;
#pragma unroll
    for (int rp = 0; rp < 16; rp++)
        Ash[rp * 256 + tid] = make_float2(g_h[(size_t)(row0 + 2 * rp) * HD + tid],
                                          g_h[(size_t)(row0 + 2 * rp + 1) * HD + tid]);
    __syncthreads();

    u64 accL[16], accR[16];
#pragma unroll
    for (int rp = 0; rp < 16; rp++) { accL[rp] = 0ull; accR[rp] = 0ull; }
    const int j = tid;

    for (int k0 = 0; k0 < 256; k0 += 2) {
        float wl0 = Wl[k0 * HD + j], wl1 = Wl[(k0 + 1) * HD + j];
        float wr0 = Wr[k0 * HD + j], wr1 = Wr[(k0 + 1) * HD + j];
        u64 wl0p = pk2(wl0, wl0), wl1p = pk2(wl1, wl1);
        u64 wr0p = pk2(wr0, wr0), wr1p = pk2(wr1, wr1);
#pragma unroll
        for (int rp = 0; rp < 16; rp++) {
            ulonglong2 a = *(const ulonglong2*)&Ash[rp * 256 + k0];
            fma2(accL[rp], a.x, wl0p);
            fma2(accL[rp], a.y, wl1p);
            fma2(accR[rp], a.x, wr0p);
            fma2(accR[rp], a.y, wr1p);
        }
    }
    float blj = bl[j], brj = br[j];
#pragma unroll
    for (int rp = 0; rp < 16; rp++) {
        float2 L = up2(accL[rp]);
        float2 R = up2(accR[rp]);
        g_xl[(size_t)(row0 + 2 * rp) * HD + j]     = L.x + blj;
        g_xl[(size_t)(row0 + 2 * rp + 1) * HD + j] = L.y + blj;
        g_xr[(size_t)(row0 + 2 * rp) * HD + j]     = R.x + brj;
        g_xr[(size_t)(row0 + 2 * rp + 1) * HD + j] = R.y + brj;
    }
}

// ================= heads =================
__global__ __launch_bounds__(128) void k_head(
    const float* __restrict__ Wc1, const float* __restrict__ bc1,
    const float* __restrict__ Wc2, const float* __restrict__ bc2,
    const float* __restrict__ Wc3, const float* __restrict__ bc3,
    const float* __restrict__ Wa1, const float* __restrict__ ba1,
    const float* __restrict__ Wa2, const float* __restrict__ ba2,
    const float* __restrict__ Wa3, const float* __restrict__ ba3,
    const int* __restrict__ action, float* __restrict__ out) {
    int b = blockIdx.x;
    int t = threadIdx.x;
    __shared__ float f[256], h1[128], h2[64], lg[NUM_ACT];

    float cnt = fmaxf(g_cnt[b], 1.0f);
    for (int j = t; j < 256; j += 128) f[j] = g_feats[b * HD + j] / cnt;
    __syncthreads();

    {   // actor
        float acc = ba1[t];
        for (int k = 0; k < 256; k++) acc += f[k] * Wa1[k * 128 + t];
        h1[t] = fmaxf(acc, 0.f);
    }
    __syncthreads();
    if (t < 64) {
        float acc = ba2[t];
        for (int k = 0; k < 128; k++) acc += h1[k] * Wa2[k * 64 + t];
        h2[t] = fmaxf(acc, 0.f);
    }
    __syncthreads();
    if (t < NUM_ACT) {
        float acc = ba3[t];
        for (int k = 0; k < 64; k++) acc += h2[k] * Wa3[k * NUM_ACT + t];
        lg[t] = acc;
        out[b * NUM_ACT + t] = acc;
    }
    __syncthreads();
    {   // critic
        float acc = bc1[t];
        for (int k = 0; k < 256; k++) acc += f[k] * Wc1[k * 128 + t];
        h1[t] = fmaxf(acc, 0.f);
    }
    __syncthreads();
    if (t < 64) {
        float acc = bc2[t];
        for (int k = 0; k < 128; k++) acc += h1[k] * Wc2[k * 64 + t];
        h2[t] = fmaxf(acc, 0.f);
    }
    __syncthreads();
    if (t == 0) {
        float v = bc3[0];
        for (int k = 0; k < 64; k++) v += h2[k] * Wc3[k];
        float mx = -INFINITY;
        for (int i = 0; i < NUM_ACT; i++) mx = fmaxf(mx, lg[i]);
        float se = 0.f;
        for (int i = 0; i < NUM_ACT; i++) se += expf(lg[i] - mx);
        float lse = logf(se) + mx;
        float ent = 0.f;
        for (int i = 0; i < NUM_ACT; i++) {
            float lp = lg[i] - lse;
            ent -= expf(lp) * lp;
        }
        out[BB * NUM_ACT + b]          = lg[action[b]] - lse;
        out[BB * NUM_ACT + BB + b]     = ent;
        out[BB * NUM_ACT + 2 * BB + b] = v;
    }
}

// ---------------- launch ----------------
extern "C" void kernel_launch(void* const* d_in, const int* in_sizes, int n_in,
                              void* d_out, int out_size) {
    const float* x      = (const float*)d_in[0];
    const int*   ei     = (const int*)  d_in[1];
    const float* ea     = (const float*)d_in[2];
    const int*   batch  = (const int*)  d_in[3];
    const int*   action = (const int*)  d_in[4];
    const float *Wl1 = (const float*)d_in[5],  *bl1 = (const float*)d_in[6];
    const float *Wr1 = (const float*)d_in[7],  *br1 = (const float*)d_in[8];
    const float *We1 = (const float*)d_in[9],  *att1 = (const float*)d_in[10], *b1 = (const float*)d_in[11];
    const float *Wl2 = (const float*)d_in[12], *bl2 = (const float*)d_in[13];
    const float *Wr2 = (const float*)d_in[14], *br2 = (const float*)d_in[15];
    const float *We2 = (const float*)d_in[16], *att2 = (const float*)d_in[17], *b2 = (const float*)d_in[18];
    const float *Wc1 = (const float*)d_in[19], *bc1 = (const float*)d_in[20];
    const float *Wc2 = (const float*)d_in[21], *bc2 = (const float*)d_in[22];
    const float *Wc3 = (const float*)d_in[23], *bc3 = (const float*)d_in[24];
    const float *Wa1 = (const float*)d_in[25], *ba1 = (const float*)d_in[26];
    const float *Wa2 = (const float*)d_in[27], *ba2 = (const float*)d_in[28];
    const float *Wa3 = (const float*)d_in[29], *ba3 = (const float*)d_in[30];
    float* out = (float*)d_out;

    void *p_deg, *p_feats, *p_cnt;
    cudaGetSymbolAddress(&p_deg,   g_deg);
    cudaGetSymbolAddress(&p_feats, g_feats);
    cudaGetSymbolAddress(&p_cnt,   g_cnt);

    static cudaStream_t s_side = nullptr;
    static cudaEvent_t ev_fork = nullptr, ev_join = nullptr;
    if (s_side == nullptr) {
        cudaStreamCreateWithFlags(&s_side, cudaStreamNonBlocking);
        cudaEventCreateWithFlags(&ev_fork, cudaEventDisableTiming);
        cudaEventCreateWithFlags(&ev_join, cudaEventDisableTiming);
    }

    // fork: layer-1 transform on side stream (overlaps CSR build)
    cudaEventRecord(ev_fork, 0);
    cudaStreamWaitEvent(s_side, ev_fork, 0);
    k_pre1<<<(NN * 64 + 255) / 256, 256, 0, s_side>>>(x, Wl1, bl1, Wr1, br1);
    cudaMemsetAsync(p_feats, 0, (size_t)BB * HD * sizeof(float), s_side);
    cudaMemsetAsync(p_cnt,   0, (size_t)BB * sizeof(float), s_side);
    cudaEventRecord(ev_join, s_side);

    // main: CSR build
    cudaMemsetAsync(p_deg, 0, NN * sizeof(int));
    k_deg<<<(EE + 255) / 256, 256>>>(ei);
    k_scan<<<1, 1024>>>();
    k_fill<<<(EE + 255) / 256, 256>>>(ei, ea);

    // join, then layer-1 fused attention
    cudaStreamWaitEvent(0, ev_join, 0);
    k_attn<0><<<NN / 4, 128>>>(We1, att1, b1, batch);

    // layer 2 transform + fused attention + pooling
    k_gemm2<<<NN / 32, 256>>>(Wl2, bl2, Wr2, br2);
    k_attn<1><<<NN / 4, 128>>>(We2, att2, b2, batch);

    // heads
    k_head<<<BB, 128>>>(Wc1, bc1, Wc2, bc2, Wc3, bc3,
                        Wa1, ba1, Wa2, ba2, Wa3, ba3, action, out);
}

// round 6
// speedup vs baseline: 3.6164x; 1.2689x over previous
#include <cuda_runtime.h>
#include <cuda_bf16.h>
#include <math.h>
#include <stdint.h>

#define NN 20000
#define EE 320000
#define BB 64
#define HD 256
#define NUM_ACT 100

typedef unsigned long long u64;

// ---------------- scratch (device globals; no allocation) ----------------
__device__ int   g_deg[NN];
__device__ int   g_rowptr[NN + 1];
__device__ int   g_cursor[NN];
__device__ __align__(16) int2 g_csr[EE];          // (src, ea bits)
__device__ __align__(16) float g_h [NN * HD];
__device__ __align__(16) float g_xl[NN * HD];
__device__ __align__(16) float g_xr[NN * HD];
__device__ __align__(16) float g_feats[BB * HD];
__device__ float g_cnt[BB];

// ---------------- helpers ----------------
__device__ __forceinline__ void red_add_v4(float* p, float a, float b, float c, float d) {
    asm volatile("red.global.add.v4.f32 [%0], {%1,%2,%3,%4};"
                 :: "l"(p), "f"(a), "f"(b), "f"(c), "f"(d) : "memory");
}
__device__ __forceinline__ u64 pk2(float x, float y) {
    u64 r;
    asm("mov.b64 %0, {%1,%2};" : "=l"(r) : "f"(x), "f"(y));
    return r;
}
__device__ __forceinline__ void fma2(u64& d, u64 a, u64 b) {
    asm("fma.rn.f32x2 %0, %1, %2, %0;" : "+l"(d) : "l"(a), "l"(b));
}
__device__ __forceinline__ u64 fma2o(u64 a, u64 b, u64 c) {
    u64 r;
    asm("fma.rn.f32x2 %0, %1, %2, %3;" : "=l"(r) : "l"(a), "l"(b), "l"(c));
    return r;
}
__device__ __forceinline__ u64 add2(u64 a, u64 b) {
    u64 r;
    asm("add.rn.f32x2 %0, %1, %2;" : "=l"(r) : "l"(a), "l"(b));
    return r;
}
__device__ __forceinline__ u64 abs2(u64 v) { return v & 0x7FFFFFFF7FFFFFFFull; }
__device__ __forceinline__ float2 up2(u64 v) {
    float2 r;
    asm("mov.b64 {%0,%1}, %2;" : "=f"(r.x), "=f"(r.y) : "l"(v));
    return r;
}
__device__ __forceinline__ uint32_t f2tf(float v) {
    uint32_t r;
    asm("cvt.rna.tf32.f32 %0, %1;" : "=r"(r) : "f"(v));
    return r;
}
__device__ __forceinline__ void mma_tf32(float c[4], uint32_t a0, uint32_t a1, uint32_t a2, uint32_t a3,
                                         uint32_t b0, uint32_t b1) {
    asm("mma.sync.aligned.m16n8k8.row.col.f32.tf32.tf32.f32 "
        "{%0,%1,%2,%3},{%4,%5,%6,%7},{%8,%9},{%0,%1,%2,%3};"
        : "+f"(c[0]), "+f"(c[1]), "+f"(c[2]), "+f"(c[3])
        : "r"(a0), "r"(a1), "r"(a2), "r"(a3), "r"(b0), "r"(b1));
}

// ================= CSR build =================
__global__ void k_deg(const int* __restrict__ ei) {
    int e = blockIdx.x * blockDim.x + threadIdx.x;
    if (e < EE) atomicAdd(&g_deg[ei[EE + e]], 1);
}

__global__ __launch_bounds__(1024) void k_scan(void) {
    __shared__ int s[1024];
    const int C = 20;
    int t = threadIdx.x;
    int base = t * C;
    int local[C];
    int sum = 0;
#pragma unroll
    for (int i = 0; i < C; i++) {
        int idx = base + i;
        int d = (idx < NN) ? g_deg[idx] : 0;
        local[i] = d;
        sum += d;
    }
    s[t] = sum;
    __syncthreads();
    for (int off = 1; off < 1024; off <<= 1) {
        int v = (t >= off) ? s[t - off] : 0;
        __syncthreads();
        s[t] += v;
        __syncthreads();
    }
    int run = (t == 0) ? 0 : s[t - 1];
#pragma unroll
    for (int i = 0; i < C; i++) {
        int idx = base + i;
        if (idx < NN) {
            g_rowptr[idx] = run;
            g_cursor[idx] = run;
            run += local[i];
        }
    }
    if (t == 1023) g_rowptr[NN] = EE;
}

__global__ void k_fill(const int* __restrict__ ei, const float* __restrict__ ea) {
    int e = blockIdx.x * blockDim.x + threadIdx.x;
    if (e >= EE) return;
    int dst = ei[EE + e];
    int pos = atomicAdd(&g_cursor[dst], 1);
    g_csr[pos] = make_int2(ei[e], __float_as_int(ea[e]));
}

// ================= layer-1 transforms (rank-4) =================
__global__ __launch_bounds__(256) void k_pre1(const float* __restrict__ x,
                                              const float* __restrict__ Wl, const float* __restrict__ bl,
                                              const float* __restrict__ Wr, const float* __restrict__ br) {
    int idx = blockIdx.x * blockDim.x + threadIdx.x;
    if (idx >= NN * 64) return;
    int n = idx >> 6;
    int c = (idx & 63) << 2;
    float4 xv = ((const float4*)x)[n];
    float xa[4] = {xv.x, xv.y, xv.z, xv.w};
    float4 l = *(const float4*)&bl[c];
    float4 r = *(const float4*)&br[c];
#pragma unroll
    for (int k = 0; k < 4; k++) {
        float4 wl = *(const float4*)&Wl[k * HD + c];
        float4 wr = *(const float4*)&Wr[k * HD + c];
        l.x += xa[k] * wl.x; l.y += xa[k] * wl.y; l.z += xa[k] * wl.z; l.w += xa[k] * wl.w;
        r.x += xa[k] * wr.x; r.y += xa[k] * wr.y; r.z += xa[k] * wr.z; r.w += xa[k] * wr.w;
    }
    ((float4*)g_xl)[idx] = l;
    ((float4*)g_xr)[idx] = r;
}

// ================= fused attention: 2 warps per node, no-max streaming softmax ==========
// global warp gw: node = gw>>1, half = gw&1; lane owns dims [half*128 + lane*4, +4).
// head = 64 dims = 16 lanes -> shfl reduce xor 1,2,4,8.
template<int POOL>
__global__ __launch_bounds__(128, 7) void k_attn(
    const float* __restrict__ We, const float* __restrict__ att,
    const float* __restrict__ bias, const int* __restrict__ batch) {
    int gw = (blockIdx.x * blockDim.x + threadIdx.x) >> 5;
    int lane = threadIdx.x & 31;
    if (gw >= 2 * NN) return;
    int n = gw >> 1;
    int half = gw & 1;
    int d0 = half * 128 + lane * 4;

    u64 We2[2], a2[2], b2[2], xr2[2];
    {
        ulonglong2 w = *(const ulonglong2*)&We[d0];
        We2[0] = w.x; We2[1] = w.y;
        float4 e = *(const float4*)&att[d0];
        a2[0] = pk2(0.6f * e.x, 0.6f * e.y); a2[1] = pk2(0.6f * e.z, 0.6f * e.w);
        b2[0] = pk2(0.4f * e.x, 0.4f * e.y); b2[1] = pk2(0.4f * e.z, 0.4f * e.w);
        ulonglong2 xr = *(const ulonglong2*)&g_xr[(size_t)n * HD + d0];
        xr2[0] = xr.x; xr2[1] = xr.y;
    }

    int beg = g_rowptr[n], end = g_rowptr[n + 1];
    float l = 0.0f;
    u64 acc2[2] = {0ull, 0ull};

    for (int i = beg; i < end; i += 4) {
        int i1 = (i + 1 < end) ? i + 1 : i;
        int i2 = (i + 2 < end) ? i + 2 : i;
        int i3 = (i + 3 < end) ? i + 3 : i;
        int2 e0 = g_csr[i], e1 = g_csr[i1], e2 = g_csr[i2], e3 = g_csr[i3];
        ulonglong2 q0 = *(const ulonglong2*)&g_xl[(size_t)e0.x * HD + d0];
        ulonglong2 q1 = *(const ulonglong2*)&g_xl[(size_t)e1.x * HD + d0];
        ulonglong2 q2 = *(const ulonglong2*)&g_xl[(size_t)e2.x * HD + d0];
        ulonglong2 q3 = *(const ulonglong2*)&g_xl[(size_t)e3.x * HD + d0];
        float ea0 = __int_as_float(e0.y), ea1 = __int_as_float(e1.y);
        float ea2 = __int_as_float(e2.y), ea3 = __int_as_float(e3.y);
        u64 ep0 = pk2(ea0, ea0), ep1 = pk2(ea1, ea1);
        u64 ep2 = pk2(ea2, ea2), ep3 = pk2(ea3, ea3);

        u64 pp0 = 0ull, pp1 = 0ull, pp2 = 0ull, pp3 = 0ull;
#pragma unroll
        for (int jp = 0; jp < 2; jp++) {
            u64 xl0 = (jp == 0) ? q0.x : q0.y;
            u64 xl1 = (jp == 0) ? q1.x : q1.y;
            u64 xl2 = (jp == 0) ? q2.x : q2.y;
            u64 xl3 = (jp == 0) ? q3.x : q3.y;
            u64 v0 = add2(fma2o(ep0, We2[jp], xr2[jp]), xl0);
            u64 v1 = add2(fma2o(ep1, We2[jp], xr2[jp]), xl1);
            u64 v2 = add2(fma2o(ep2, We2[jp], xr2[jp]), xl2);
            u64 v3 = add2(fma2o(ep3, We2[jp], xr2[jp]), xl3);
            fma2(pp0, a2[jp], v0); fma2(pp0, b2[jp], abs2(v0));
            fma2(pp1, a2[jp], v1); fma2(pp1, b2[jp], abs2(v1));
            fma2(pp2, a2[jp], v2); fma2(pp2, b2[jp], abs2(v2));
            fma2(pp3, a2[jp], v3); fma2(pp3, b2[jp], abs2(v3));
        }
        float2 f0 = up2(pp0), f1 = up2(pp1), f2 = up2(pp2), f3 = up2(pp3);
        float p0 = f0.x + f0.y, p1 = f1.x + f1.y, p2 = f2.x + f2.y, p3 = f3.x + f3.y;
#pragma unroll
        for (int o = 1; o <= 8; o <<= 1) {
            p0 += __shfl_xor_sync(0xffffffffu, p0, o);
            p1 += __shfl_xor_sync(0xffffffffu, p1, o);
            p2 += __shfl_xor_sync(0xffffffffu, p2, o);
            p3 += __shfl_xor_sync(0xffffffffu, p3, o);
        }
        if (i + 1 >= end) p1 = -INFINITY;
        if (i + 2 >= end) p2 = -INFINITY;
        if (i + 3 >= end) p3 = -INFINITY;

        // no-max softmax (scores bounded; shift-invariance unused)
        float w0 = __expf(p0), w1 = __expf(p1), w2 = __expf(p2), w3 = __expf(p3);
        l += (w0 + w1) + (w2 + w3);
        u64 wp0 = pk2(w0, w0), wp1 = pk2(w1, w1), wp2 = pk2(w2, w2), wp3 = pk2(w3, w3);
        fma2(acc2[0], wp0, q0.x); fma2(acc2[1], wp0, q0.y);
        fma2(acc2[0], wp1, q1.x); fma2(acc2[1], wp1, q1.y);
        fma2(acc2[0], wp2, q2.x); fma2(acc2[1], wp2, q2.y);
        fma2(acc2[0], wp3, q3.x); fma2(acc2[1], wp3, q3.y);
    }
    float inv = 1.0f / (l + 1e-16f);
    float2 c0 = up2(acc2[0]), c1 = up2(acc2[1]);
    float4 ba = *(const float4*)&bias[d0];
    float v0 = fmaxf(fmaf(c0.x, inv, ba.x), 0.f);
    float v1 = fmaxf(fmaf(c0.y, inv, ba.y), 0.f);
    float v2 = fmaxf(fmaf(c1.x, inv, ba.z), 0.f);
    float v3 = fmaxf(fmaf(c1.y, inv, ba.w), 0.f);
    if (POOL == 0) {
        *(float4*)&g_h[(size_t)n * HD + d0] = make_float4(v0, v1, v2, v3);
    } else {
        int b = batch[n];
        red_add_v4(&g_feats[b * HD + d0], v0, v1, v2, v3);
        if (lane == 0 && half == 0) atomicAdd(&g_cnt[b], 1.0f);
    }
}

// ================= layer-2 dual GEMM: 3xTF32 tensor cores =================
// Block: 256 thr (8 warps 2x4), tile 64M x 128N, BK=16, 16 k-stages.
// grid = (ceil(NN/64), 4): bn 0,1 -> Wl -> g_xl; bn 2,3 -> Wr -> g_xr.
__global__ __launch_bounds__(256) void k_gemm2t(const float* __restrict__ Wl, const float* __restrict__ bl,
                                                const float* __restrict__ Wr, const float* __restrict__ br) {
    __shared__ float As_hi[64][20], As_lo[64][20];
    __shared__ float Bs_hi[16][136], Bs_lo[16][136];
    int tid = threadIdx.x;
    int warp = tid >> 5, lane = tid & 31;
    int wm = warp & 1, wn = warp >> 1;          // 2 x 4 warp grid
    int g = lane >> 2, t = lane & 3;
    int row0 = blockIdx.x * 64;
    int bn = blockIdx.y;
    const float* W    = (bn < 2) ? Wl : Wr;
    const float* bias = (bn < 2) ? bl : br;
    float* Out        = (bn < 2) ? g_xl : g_xr;
    int n0 = (bn & 1) * 128;

    float c[2][4][4];
#pragma unroll
    for (int mm = 0; mm < 2; mm++)
#pragma unroll
        for (int nn = 0; nn < 4; nn++)
#pragma unroll
            for (int q = 0; q < 4; q++) c[mm][nn][q] = 0.0f;

    for (int ks = 0; ks < 16; ks++) {
        // stage A: 64 rows x 16 k = 256 float4, 1 per thread
        {
            int row = tid >> 2;
            int kq = tid & 3;
            int grow = row0 + row;
            float4 v = (grow < NN) ? *(const float4*)&g_h[(size_t)grow * HD + ks * 16 + kq * 4]
                                   : make_float4(0.f, 0.f, 0.f, 0.f);
            float hx = __uint_as_float(f2tf(v.x)), hy = __uint_as_float(f2tf(v.y));
            float hz = __uint_as_float(f2tf(v.z)), hw = __uint_as_float(f2tf(v.w));
            *(float4*)&As_hi[row][kq * 4] = make_float4(hx, hy, hz, hw);
            *(float4*)&As_lo[row][kq * 4] = make_float4(
                __uint_as_float(f2tf(v.x - hx)), __uint_as_float(f2tf(v.y - hy)),
                __uint_as_float(f2tf(v.z - hz)), __uint_as_float(f2tf(v.w - hw)));
        }
        // stage B: 16 rows x 128 n = 512 float4, 2 per thread
#pragma unroll
        for (int r = 0; r < 2; r++) {
            int idx = tid + 256 * r;
            int row = idx >> 5;
            int nq = idx & 31;
            float4 v = *(const float4*)&W[(size_t)(ks * 16 + row) * 256 + n0 + nq * 4];
            float hx = __uint_as_float(f2tf(v.x)), hy = __uint_as_float(f2tf(v.y));
            float hz = __uint_as_float(f2tf(v.z)), hw = __uint_as_float(f2tf(v.w));
            *(float4*)&Bs_hi[row][nq * 4] = make_float4(hx, hy, hz, hw);
            *(float4*)&Bs_lo[row][nq * 4] = make_float4(
                __uint_as_float(f2tf(v.x - hx)), __uint_as_float(f2tf(v.y - hy)),
                __uint_as_float(f2tf(v.z - hz)), __uint_as_float(f2tf(v.w - hw)));
        }
        __syncthreads();

#pragma unroll
        for (int k8 = 0; k8 < 2; k8++) {
            int kb = k8 * 8;
            uint32_t ahi[2][4], alo[2][4];
#pragma unroll
            for (int mm = 0; mm < 2; mm++) {
                int rb = wm * 32 + mm * 16;
                ahi[mm][0] = __float_as_uint(As_hi[rb + g][kb + t]);
                ahi[mm][1] = __float_as_uint(As_hi[rb + g + 8][kb + t]);
                ahi[mm][2] = __float_as_uint(As_hi[rb + g][kb + t + 4]);
                ahi[mm][3] = __float_as_uint(As_hi[rb + g + 8][kb + t + 4]);
                alo[mm][0] = __float_as_uint(As_lo[rb + g][kb + t]);
                alo[mm][1] = __float_as_uint(As_lo[rb + g + 8][kb + t]);
                alo[mm][2] = __float_as_uint(As_lo[rb + g][kb + t + 4]);
                alo[mm][3] = __float_as_uint(As_lo[rb + g + 8][kb + t + 4]);
            }
#pragma unroll
            for (int nn = 0; nn < 4; nn++) {
                int nb = wn * 32 + nn * 8 + g;
                uint32_t bhi0 = __float_as_uint(Bs_hi[kb + t][nb]);
                uint32_t bhi1 = __float_as_uint(Bs_hi[kb + t + 4][nb]);
                uint32_t blo0 = __float_as_uint(Bs_lo[kb + t][nb]);
                uint32_t blo1 = __float_as_uint(Bs_lo[kb + t + 4][nb]);
#pragma unroll
                for (int mm = 0; mm < 2; mm++) {
                    mma_tf32(c[mm][nn], alo[mm][0], alo[mm][1], alo[mm][2], alo[mm][3], bhi0, bhi1);
                    mma_tf32(c[mm][nn], ahi[mm][0], ahi[mm][1], ahi[mm][2], ahi[mm][3], blo0, blo1);
                    mma_tf32(c[mm][nn], ahi[mm][0], ahi[mm][1], ahi[mm][2], ahi[mm][3], bhi0, bhi1);
                }
            }
        }
        __syncthreads();
    }

    // epilogue: bias + store (pairs of contiguous cols)
#pragma unroll
    for (int mm = 0; mm < 2; mm++) {
#pragma unroll
        for (int nn = 0; nn < 4; nn++) {
            int cg = n0 + wn * 32 + nn * 8 + 2 * t;
            float b0 = bias[cg], b1 = bias[cg + 1];
            int r0 = row0 + wm * 32 + mm * 16 + g;
            int r1 = r0 + 8;
            if (r0 < NN)
                *(float2*)&Out[(size_t)r0 * HD + (cg & 255)] =
                    make_float2(c[mm][nn][0] + b0, c[mm][nn][1] + b1);
            if (r1 < NN)
                *(float2*)&Out[(size_t)r1 * HD + (cg & 255)] =
                    make_float2(c[mm][nn][2] + b0, c[mm][nn][3] + b1);
        }
    }
}

// ================= heads =================
__global__ __launch_bounds__(128) void k_head(
    const float* __restrict__ Wc1, const float* __restrict__ bc1,
    const float* __restrict__ Wc2, const float* __restrict__ bc2,
    const float* __restrict__ Wc3, const float* __restrict__ bc3,
    const float* __restrict__ Wa1, const float* __restrict__ ba1,
    const float* __restrict__ Wa2, const float* __restrict__ ba2,
    const float* __restrict__ Wa3, const float* __restrict__ ba3,
    const int* __restrict__ action, float* __restrict__ out) {
    int b = blockIdx.x;
    int t = threadIdx.x;
    __shared__ float f[256], h1[128], h2[64], lg[NUM_ACT];

    float cnt = fmaxf(g_cnt[b], 1.0f);
    for (int j = t; j < 256; j += 128) f[j] = g_feats[b * HD + j] / cnt;
    __syncthreads();

    {   // actor
        float acc = ba1[t];
        for (int k = 0; k < 256; k++) acc += f[k] * Wa1[k * 128 + t];
        h1[t] = fmaxf(acc, 0.f);
    }
    __syncthreads();
    if (t < 64) {
        float acc = ba2[t];
        for (int k = 0; k < 128; k++) acc += h1[k] * Wa2[k * 64 + t];
        h2[t] = fmaxf(acc, 0.f);
    }
    __syncthreads();
    if (t < NUM_ACT) {
        float acc = ba3[t];
        for (int k = 0; k < 64; k++) acc += h2[k] * Wa3[k * NUM_ACT + t];
        lg[t] = acc;
        out[b * NUM_ACT + t] = acc;
    }
    __syncthreads();
    {   // critic
        float acc = bc1[t];
        for (int k = 0; k < 256; k++) acc += f[k] * Wc1[k * 128 + t];
        h1[t] = fmaxf(acc, 0.f);
    }
    __syncthreads();
    if (t < 64) {
        float acc = bc2[t];
        for (int k = 0; k < 128; k++) acc += h1[k] * Wc2[k * 64 + t];
        h2[t] = fmaxf(acc, 0.f);
    }
    __syncthreads();
    if (t == 0) {
        float v = bc3[0];
        for (int k = 0; k < 64; k++) v += h2[k] * Wc3[k];
        float mx = -INFINITY;
        for (int i = 0; i < NUM_ACT; i++) mx = fmaxf(mx, lg[i]);
        float se = 0.f;
        for (int i = 0; i < NUM_ACT; i++) se += expf(lg[i] - mx);
        float lse = logf(se) + mx;
        float ent = 0.f;
        for (int i = 0; i < NUM_ACT; i++) {
            float lp = lg[i] - lse;
            ent -= expf(lp) * lp;
        }
        out[BB * NUM_ACT + b]          = lg[action[b]] - lse;
        out[BB * NUM_ACT + BB + b]     = ent;
        out[BB * NUM_ACT + 2 * BB + b] = v;
    }
}

// ---------------- launch ----------------
extern "C" void kernel_launch(void* const* d_in, const int* in_sizes, int n_in,
                              void* d_out, int out_size) {
    const float* x      = (const float*)d_in[0];
    const int*   ei     = (const int*)  d_in[1];
    const float* ea     = (const float*)d_in[2];
    const int*   batch  = (const int*)  d_in[3];
    const int*   action = (const int*)  d_in[4];
    const float *Wl1 = (const float*)d_in[5],  *bl1 = (const float*)d_in[6];
    const float *Wr1 = (const float*)d_in[7],  *br1 = (const float*)d_in[8];
    const float *We1 = (const float*)d_in[9],  *att1 = (const float*)d_in[10], *b1 = (const float*)d_in[11];
    const float *Wl2 = (const float*)d_in[12], *bl2 = (const float*)d_in[13];
    const float *Wr2 = (const float*)d_in[14], *br2 = (const float*)d_in[15];
    const float *We2 = (const float*)d_in[16], *att2 = (const float*)d_in[17], *b2 = (const float*)d_in[18];
    const float *Wc1 = (const float*)d_in[19], *bc1 = (const float*)d_in[20];
    const float *Wc2 = (const float*)d_in[21], *bc2 = (const float*)d_in[22];
    const float *Wc3 = (const float*)d_in[23], *bc3 = (const float*)d_in[24];
    const float *Wa1 = (const float*)d_in[25], *ba1 = (const float*)d_in[26];
    const float *Wa2 = (const float*)d_in[27], *ba2 = (const float*)d_in[28];
    const float *Wa3 = (const float*)d_in[29], *ba3 = (const float*)d_in[30];
    float* out = (float*)d_out;

    void *p_deg, *p_feats, *p_cnt;
    cudaGetSymbolAddress(&p_deg,   g_deg);
    cudaGetSymbolAddress(&p_feats, g_feats);
    cudaGetSymbolAddress(&p_cnt,   g_cnt);

    static cudaStream_t s_side = nullptr;
    static cudaEvent_t ev_fork = nullptr, ev_join = nullptr;
    if (s_side == nullptr) {
        cudaStreamCreateWithFlags(&s_side, cudaStreamNonBlocking);
        cudaEventCreateWithFlags(&ev_fork, cudaEventDisableTiming);
        cudaEventCreateWithFlags(&ev_join, cudaEventDisableTiming);
    }

    // fork: layer-1 transform on side stream (overlaps CSR build)
    cudaEventRecord(ev_fork, 0);
    cudaStreamWaitEvent(s_side, ev_fork, 0);
    k_pre1<<<(NN * 64 + 255) / 256, 256, 0, s_side>>>(x, Wl1, bl1, Wr1, br1);
    cudaMemsetAsync(p_feats, 0, (size_t)BB * HD * sizeof(float), s_side);
    cudaMemsetAsync(p_cnt,   0, (size_t)BB * sizeof(float), s_side);
    cudaEventRecord(ev_join, s_side);

    // main: CSR build
    cudaMemsetAsync(p_deg, 0, NN * sizeof(int));
    k_deg<<<(EE + 255) / 256, 256>>>(ei);
    k_scan<<<1, 1024>>>();
    k_fill<<<(EE + 255) / 256, 256>>>(ei, ea);

    // join, then layer-1 fused attention (2 warps/node)
    cudaStreamWaitEvent(0, ev_join, 0);
    k_attn<0><<<(2 * NN) / 4, 128>>>(We1, att1, b1, batch);

    // layer 2 transform (3xTF32 tensor cores) + fused attention + pooling
    k_gemm2t<<<dim3((NN + 63) / 64, 4), 256>>>(Wl2, bl2, Wr2, br2);
    k_attn<1><<<(2 * NN) / 4, 128>>>(We2, att2, b2, batch);

    // heads
    k_head<<<BB, 128>>>(Wc1, bc1, Wc2, bc2, Wc3, bc3,
                        Wa1, ba1, Wa2, ba2, Wa3, ba3, action, out);
}